// round 4
// baseline (speedup 1.0000x reference)
#include <cuda_runtime.h>
#include <math.h>

// Problem constants
#define BATCH 8
#define NTOK 1024
#define DIMC 512
#define NH 16
#define HD 32
#define TABLE_SZ 3969
#define SEQ_SCALE 6.93147180559945309f  // ln(1024)

// ---------------- scratch (device globals; no allocation allowed) -------------
__device__ float g_scale[NH];
__device__ float g_t[TABLE_SZ * NH];
__device__ float g_bias[NH * NTOK * NTOK];          // [h][n][m] 64MB
__device__ float g_qkv[BATCH * NTOK * 3 * DIMC];    // 50MB
__device__ unsigned g_qh[BATCH * NH * NTOK * HD];   // pre-split q hi
__device__ unsigned g_ql[BATCH * NH * NTOK * HD];   // pre-split q lo
__device__ unsigned g_kh[BATCH * NH * NTOK * HD];   // pre-split k hi
__device__ unsigned g_kl[BATCH * NH * NTOK * HD];   // pre-split k lo
__device__ unsigned g_vt[BATCH * NH * NTOK * HD];   // v tf32
__device__ unsigned g_oh[BATCH * NTOK * DIMC];      // attn out hi
__device__ unsigned g_ol[BATCH * NTOK * DIMC];      // attn out lo
__device__ unsigned g_xh[BATCH * NTOK * DIMC];      // x hi
__device__ unsigned g_xl[BATCH * NTOK * DIMC];      // x lo
__device__ unsigned g_wh[(3 * DIMC + DIMC) * DIMC]; // W hi (qkv then proj)
__device__ unsigned g_wl[(3 * DIMC + DIMC) * DIMC]; // W lo

// ---------------- tf32 / cp.async helpers ------------------------------------
__device__ __forceinline__ unsigned tf32_rna(float x) {
    unsigned r; asm("cvt.rna.tf32.f32 %0, %1;" : "=r"(r) : "f"(x)); return r;
}
__device__ __forceinline__ void tf32_split(float x, unsigned& hi, unsigned& lo) {
    hi = tf32_rna(x);
    lo = tf32_rna(x - __uint_as_float(hi));
}
__device__ __forceinline__ void mma8(float* c, const unsigned* a, const unsigned* b) {
    asm volatile("mma.sync.aligned.m16n8k8.row.col.f32.tf32.tf32.f32 "
                 "{%0,%1,%2,%3}, {%4,%5,%6,%7}, {%8,%9}, {%0,%1,%2,%3};"
                 : "+f"(c[0]), "+f"(c[1]), "+f"(c[2]), "+f"(c[3])
                 : "r"(a[0]), "r"(a[1]), "r"(a[2]), "r"(a[3]),
                   "r"(b[0]), "r"(b[1]));
}
__device__ __forceinline__ void cp16(void* sdst, const void* gsrc) {
    unsigned u = (unsigned)__cvta_generic_to_shared(sdst);
    asm volatile("cp.async.ca.shared.global [%0], [%1], 16;" :: "r"(u), "l"(gsrc));
}
#define CP_COMMIT() asm volatile("cp.async.commit_group;")
#define CP_WAIT(n)  asm volatile("cp.async.wait_group %0;" :: "n"(n))

// ---------------- kernel 1: scale = softplus(temperature) * ln(N) ------------
__global__ void scale_kernel(const float* __restrict__ temp) {
    int h = threadIdx.x;
    if (h < NH) {
        float t = temp[h];
        float sp = (t > 20.0f) ? t : log1pf(expf(t));
        g_scale[h] = sp * SEQ_SCALE;
    }
}

// ---------------- pre-split weights ------------------------------------------
__global__ void wsplit_kernel(const float* __restrict__ qkvw,
                              const float* __restrict__ projw) {
    int i = blockIdx.x * 256 + threadIdx.x;
    int nq = 3 * DIMC * DIMC;
    int np = DIMC * DIMC;
    if (i < nq) {
        unsigned h, l; tf32_split(qkvw[i], h, l);
        g_wh[i] = h; g_wl[i] = l;
    } else if (i < nq + np) {
        unsigned h, l; tf32_split(projw[i - nq], h, l);
        g_wh[i] = h; g_wl[i] = l;
    }
}

// ---------------- pre-split x (float4 vectorized) -----------------------------
__global__ void xsplit_kernel(const float* __restrict__ x) {
    int i = blockIdx.x * 256 + threadIdx.x;     // i indexes float4 groups
    float4 v = ((const float4*)x)[i];
    unsigned h0, l0, h1, l1, h2, l2, h3, l3;
    tf32_split(v.x, h0, l0); tf32_split(v.y, h1, l1);
    tf32_split(v.z, h2, l2); tf32_split(v.w, h3, l3);
    ((uint4*)g_xh)[i] = make_uint4(h0, h1, h2, h3);
    ((uint4*)g_xl)[i] = make_uint4(l0, l1, l2, l3);
}

// ---------------- kernel 2: CPB MLP  t[r][h] ---------------------------------
__global__ void cpb_kernel(const float* __restrict__ table,
                           const float* __restrict__ fc1w,
                           const float* __restrict__ fc1b,
                           const float* __restrict__ fc2w,
                           const float* __restrict__ fc2b) {
    __shared__ float hid[512];
    int r = blockIdx.x;
    int j = threadIdx.x;
    float c0 = table[r * 2 + 0];
    float c1 = table[r * 2 + 1];
    float hv = c0 * fc1w[j * 2 + 0] + c1 * fc1w[j * 2 + 1] + fc1b[j];
    hid[j] = fmaxf(hv, 0.0f);
    __syncthreads();
    int w = j >> 5;
    int lane = j & 31;
    float acc = 0.0f;
#pragma unroll
    for (int kk = lane; kk < 512; kk += 32) acc += hid[kk] * fc2w[w * 512 + kk];
#pragma unroll
    for (int off = 16; off >= 1; off >>= 1) acc += __shfl_xor_sync(0xffffffffu, acc, off);
    if (lane == 0) g_t[r * NH + w] = acc + fc2b[w];
}

// ---------------- kernel 3: bias gather  bias[h][n][m] = t[rpi[n][m]][h] -----
__global__ void bias_kernel(const int* __restrict__ rpi) {
    int n = blockIdx.x;
    for (int m = threadIdx.x; m < NTOK; m += blockDim.x) {
        int idx = rpi[n * NTOK + m];
        const float4* tp = (const float4*)(g_t + idx * NH);
        float4 t0 = tp[0], t1 = tp[1], t2 = tp[2], t3 = tp[3];
        float v[16] = {t0.x, t0.y, t0.z, t0.w, t1.x, t1.y, t1.z, t1.w,
                       t2.x, t2.y, t2.z, t2.w, t3.x, t3.y, t3.z, t3.w};
#pragma unroll
        for (int h = 0; h < NH; h++)
            g_bias[(h * NTOK + n) * NTOK + m] = v[h];
    }
}

// ---------------- 3xTF32 GEMM, all operands pre-split, cp.async 2-stage -------
// BM=BN=128, BK=16, 256 threads, 8 warps 4x2, warp tile 32x64.
// dyn smem: Ahs/Als/Whs/Wls each [2][128][20] u32
#define GEMM_SMEM (4 * 2 * 128 * 20 * 4)
__global__ __launch_bounds__(256, 2) void gemm3s(const unsigned* __restrict__ Ah,
                                                 const unsigned* __restrict__ Al,
                                                 const unsigned* __restrict__ Wh,
                                                 const unsigned* __restrict__ Wl,
                                                 const float* __restrict__ bias,
                                                 float* __restrict__ C,
                                                 int M, int Nn, int K) {
    extern __shared__ unsigned smg[];
    unsigned* Ahs = smg;              // [2][2560]
    unsigned* Als = smg + 2 * 2560;
    unsigned* Whs = smg + 4 * 2560;
    unsigned* Wls = smg + 6 * 2560;

    int tid = threadIdx.x;
    int wid = tid >> 5, lane = tid & 31;
    int g = lane >> 2, tg = lane & 3;
    int wm = wid & 3, wn = wid >> 2;
    int m0 = blockIdx.y * 128, n0 = blockIdx.x * 128;

    int lrow0 = tid >> 2, lch0 = (tid & 3) * 4;          // chunk tid
    int lrow1 = (tid + 256) >> 2;                        // chunk tid+256 (same lch)

    float acc[2][8][4];
#pragma unroll
    for (int mi = 0; mi < 2; mi++)
#pragma unroll
        for (int j = 0; j < 8; j++)
#pragma unroll
            for (int c = 0; c < 4; c++) acc[mi][j][c] = 0.0f;

    int nk = K >> 4;
#define G_LOAD(stage, kk0)                                                        \
    do {                                                                          \
        cp16(&Ahs[(stage) * 2560 + lrow0 * 20 + lch0], Ah + (size_t)(m0 + lrow0) * K + (kk0) + lch0); \
        cp16(&Ahs[(stage) * 2560 + lrow1 * 20 + lch0], Ah + (size_t)(m0 + lrow1) * K + (kk0) + lch0); \
        cp16(&Als[(stage) * 2560 + lrow0 * 20 + lch0], Al + (size_t)(m0 + lrow0) * K + (kk0) + lch0); \
        cp16(&Als[(stage) * 2560 + lrow1 * 20 + lch0], Al + (size_t)(m0 + lrow1) * K + (kk0) + lch0); \
        cp16(&Whs[(stage) * 2560 + lrow0 * 20 + lch0], Wh + (size_t)(n0 + lrow0) * K + (kk0) + lch0); \
        cp16(&Whs[(stage) * 2560 + lrow1 * 20 + lch0], Wh + (size_t)(n0 + lrow1) * K + (kk0) + lch0); \
        cp16(&Wls[(stage) * 2560 + lrow0 * 20 + lch0], Wl + (size_t)(n0 + lrow0) * K + (kk0) + lch0); \
        cp16(&Wls[(stage) * 2560 + lrow1 * 20 + lch0], Wl + (size_t)(n0 + lrow1) * K + (kk0) + lch0); \
        CP_COMMIT();                                                              \
    } while (0)

    G_LOAD(0, 0);

    for (int i = 0; i < nk; i++) {
        if (i + 1 < nk) {
            G_LOAD((i + 1) & 1, (i + 1) << 4);
            CP_WAIT(1);
        } else {
            CP_WAIT(0);
        }
        __syncthreads();
        int s = i & 1;
        const unsigned* Ahb = Ahs + s * 2560;
        const unsigned* Alb = Als + s * 2560;
        const unsigned* Whb = Whs + s * 2560;
        const unsigned* Wlb = Wls + s * 2560;
#pragma unroll
        for (int kt = 0; kt < 2; kt++) {
            int kc = kt * 8 + tg;
            unsigned ah[2][4], al[2][4];
#pragma unroll
            for (int mi = 0; mi < 2; mi++) {
                int r = wm * 32 + mi * 16 + g;
                ah[mi][0] = Ahb[r * 20 + kc];       al[mi][0] = Alb[r * 20 + kc];
                ah[mi][1] = Ahb[(r + 8) * 20 + kc]; al[mi][1] = Alb[(r + 8) * 20 + kc];
                ah[mi][2] = Ahb[r * 20 + kc + 4];   al[mi][2] = Alb[r * 20 + kc + 4];
                ah[mi][3] = Ahb[(r + 8) * 20 + kc + 4]; al[mi][3] = Alb[(r + 8) * 20 + kc + 4];
            }
#pragma unroll
            for (int j = 0; j < 8; j++) {
                int col = wn * 64 + j * 8 + g;
                unsigned bh[2] = {Whb[col * 20 + kc], Whb[col * 20 + kc + 4]};
                unsigned bl[2] = {Wlb[col * 20 + kc], Wlb[col * 20 + kc + 4]};
#pragma unroll
                for (int mi = 0; mi < 2; mi++) {
                    mma8(acc[mi][j], ah[mi], bh);
                    mma8(acc[mi][j], ah[mi], bl);
                    mma8(acc[mi][j], al[mi], bh);
                }
            }
        }
        __syncthreads();
    }
    // epilogue
#pragma unroll
    for (int j = 0; j < 8; j++) {
        int col = n0 + wn * 64 + j * 8 + tg * 2;
        float2 bv = *(const float2*)(bias + col);
#pragma unroll
        for (int mi = 0; mi < 2; mi++) {
            int row = m0 + wm * 32 + mi * 16 + g;
            float2 o0 = make_float2(acc[mi][j][0] + bv.x, acc[mi][j][1] + bv.y);
            float2 o1 = make_float2(acc[mi][j][2] + bv.x, acc[mi][j][3] + bv.y);
            *(float2*)(C + (size_t)row * Nn + col) = o0;
            *(float2*)(C + (size_t)(row + 8) * Nn + col) = o1;
        }
    }
}

// ---------------- reorg: normalize q/k, pre-split, repack to [b,h,n,d] -------
__global__ void reorg_kernel(const float* __restrict__ qe) {
    int wg = blockIdx.x * 8 + (threadIdx.x >> 5);
    int lane = threadIdx.x & 31;
    int h = wg & 15;
    int bn = wg >> 4;
    int b = bn >> 10;
    int n = bn & 1023;
    const float* base = g_qkv + (size_t)bn * (3 * DIMC);
    float q = base[h * HD + lane];
    float k = base[DIMC + h * HD + lane];
    float v = base[2 * DIMC + h * HD + lane];

    float s = q * q;
#pragma unroll
    for (int off = 16; off >= 1; off >>= 1) s += __shfl_xor_sync(0xffffffffu, s, off);
    float qn = q / fmaxf(sqrtf(s), 1e-12f);
    qn = (qn + qe[h * HD + lane]) * g_scale[h];

    s = k * k;
#pragma unroll
    for (int off = 16; off >= 1; off >>= 1) s += __shfl_xor_sync(0xffffffffu, s, off);
    float kn = k / fmaxf(sqrtf(s), 1e-12f);

    size_t idx = ((size_t)(b * NH + h) * NTOK + n) * HD + lane;
    unsigned hh, ll;
    tf32_split(qn, hh, ll);
    g_qh[idx] = hh; g_ql[idx] = ll;
    tf32_split(kn, hh, ll);
    g_kh[idx] = hh; g_kl[idx] = ll;
    g_vt[idx] = tf32_rna(v);
}

// ---------------- attention v4: fully pre-split, cp.async KV + bias -----------
// grid (B, N/128, H), 256 threads, 128 queries/block, key tiles 64.
// dyn smem: Ksh/Ksl/Vs each [2][64][36] u32, BP[128][68] f32
#define ATTN_SMEM ((6 * 2304 + 128 * 68) * 4)
__global__ __launch_bounds__(256, 2) void attn4_kernel() {
    extern __shared__ unsigned smu[];
    unsigned* Ksh = smu;               // [2][2304]
    unsigned* Ksl = smu + 2 * 2304;
    unsigned* Vs  = smu + 4 * 2304;
    float* BP = (float*)(smu + 6 * 2304);
    unsigned* BPu = (unsigned*)BP;

    int b = blockIdx.x, qt = blockIdx.y, h = blockIdx.z;
    int tid = threadIdx.x;
    int w = tid >> 5, lane = tid & 31;
    int g = lane >> 2, tg = lane & 3;

    size_t bh_off = (size_t)(b * NH + h) * NTOK * HD;
    const unsigned* qhb = g_qh + bh_off + (size_t)qt * 128 * HD;
    const unsigned* qlb = g_ql + bh_off + (size_t)qt * 128 * HD;
    const unsigned* khb = g_kh + bh_off;
    const unsigned* klb = g_kl + bh_off;
    const unsigned* vtb = g_vt + bh_off;
    const float* bbase = g_bias + ((size_t)h * NTOK + qt * 128) * NTOK;

    // K/V loader mapping: 512 16B-chunks per array, 2 per thread
    int krow0 = tid >> 3, kch0 = (tid & 7) * 4;
    int krow1 = krow0 + 32;
#define KV_LOAD(stage, mt_)                                                       \
    do {                                                                          \
        const unsigned* kb = khb + (size_t)(mt_) * 64 * HD;                       \
        const unsigned* lb = klb + (size_t)(mt_) * 64 * HD;                       \
        const unsigned* vb = vtb + (size_t)(mt_) * 64 * HD;                       \
        cp16(&Ksh[(stage) * 2304 + krow0 * 36 + kch0], kb + krow0 * HD + kch0);   \
        cp16(&Ksh[(stage) * 2304 + krow1 * 36 + kch0], kb + krow1 * HD + kch0);   \
        cp16(&Ksl[(stage) * 2304 + krow0 * 36 + kch0], lb + krow0 * HD + kch0);   \
        cp16(&Ksl[(stage) * 2304 + krow1 * 36 + kch0], lb + krow1 * HD + kch0);   \
        cp16(&Vs[(stage) * 2304 + krow0 * 36 + kch0], vb + krow0 * HD + kch0);    \
        cp16(&Vs[(stage) * 2304 + krow1 * 36 + kch0], vb + krow1 * HD + kch0);    \
        CP_COMMIT();                                                              \
    } while (0)

    KV_LOAD(0, 0);

    // Q fragments: direct pre-split loads
    unsigned Qh[4][4], Ql[4][4];
#pragma unroll
    for (int kt = 0; kt < 4; kt++) {
        int c = kt * 8 + tg;
        int r = w * 16 + g;
        Qh[kt][0] = qhb[r * HD + c];           Ql[kt][0] = qlb[r * HD + c];
        Qh[kt][1] = qhb[(r + 8) * HD + c];     Ql[kt][1] = qlb[(r + 8) * HD + c];
        Qh[kt][2] = qhb[r * HD + c + 4];       Ql[kt][2] = qlb[r * HD + c + 4];
        Qh[kt][3] = qhb[(r + 8) * HD + c + 4]; Ql[kt][3] = qlb[(r + 8) * HD + c + 4];
    }

    float m0 = -INFINITY, m1 = -INFINITY, l0 = 0.0f, l1 = 0.0f;
    float O[4][4];
#pragma unroll
    for (int j = 0; j < 4; j++)
#pragma unroll
        for (int c = 0; c < 4; c++) O[j][c] = 0.0f;

    int bc = (tid & 15) * 4, br = tid >> 4;   // bias loaders

    for (int mt = 0; mt < 16; mt++) {
        int s = mt & 1;
        __syncthreads();   // P from prev tile consumed; BP free
        // bias(mt) as its own cp.async group — flies during QK
#pragma unroll
        for (int p = 0; p < 8; p++) {
            int row = br + p * 16;
            cp16(&BP[row * 68 + bc], bbase + (size_t)row * NTOK + mt * 64 + bc);
        }
        CP_COMMIT();
        if (mt + 1 < 16) {
            KV_LOAD(s ^ 1, mt + 1);
            CP_WAIT(2);    // KV(mt) done; bias + KV(mt+1) in flight
        } else {
            CP_WAIT(1);    // KV(15) done
        }
        __syncthreads();

        // QK^T: 3xTF32 (bias still loading)
        float S[8][4];
#pragma unroll
        for (int j = 0; j < 8; j++)
#pragma unroll
            for (int c = 0; c < 4; c++) S[j][c] = 0.0f;
        const unsigned* Khb = Ksh + s * 2304;
        const unsigned* Klb = Ksl + s * 2304;
#pragma unroll
        for (int kt = 0; kt < 4; kt++) {
            int kc = kt * 8 + tg;
#pragma unroll
            for (int j = 0; j < 8; j++) {
                int key = j * 8 + g;
                unsigned bhf[2] = {Khb[key * 36 + kc], Khb[key * 36 + kc + 4]};
                unsigned blf[2] = {Klb[key * 36 + kc], Klb[key * 36 + kc + 4]};
                mma8(S[j], Qh[kt], bhf);
                mma8(S[j], Qh[kt], blf);
                mma8(S[j], Ql[kt], bhf);
            }
        }
        if (mt + 1 < 16) { CP_WAIT(1); } else { CP_WAIT(0); }
        __syncthreads();   // bias visible to all
        // bias add
#pragma unroll
        for (int j = 0; j < 8; j++) {
            int r = w * 16 + g;
            float2 b0 = *(const float2*)(BP + r * 68 + j * 8 + tg * 2);
            float2 b1 = *(const float2*)(BP + (r + 8) * 68 + j * 8 + tg * 2);
            S[j][0] += b0.x; S[j][1] += b0.y;
            S[j][2] += b1.x; S[j][3] += b1.y;
        }
        // online softmax
        float mx0 = -INFINITY, mx1 = -INFINITY;
#pragma unroll
        for (int j = 0; j < 8; j++) {
            mx0 = fmaxf(mx0, fmaxf(S[j][0], S[j][1]));
            mx1 = fmaxf(mx1, fmaxf(S[j][2], S[j][3]));
        }
        mx0 = fmaxf(mx0, __shfl_xor_sync(0xffffffffu, mx0, 1));
        mx0 = fmaxf(mx0, __shfl_xor_sync(0xffffffffu, mx0, 2));
        mx1 = fmaxf(mx1, __shfl_xor_sync(0xffffffffu, mx1, 1));
        mx1 = fmaxf(mx1, __shfl_xor_sync(0xffffffffu, mx1, 2));
        float mn0 = fmaxf(m0, mx0), mn1 = fmaxf(m1, mx1);
        float alpha0 = __expf(m0 - mn0), alpha1 = __expf(m1 - mn1);
        m0 = mn0; m1 = mn1;
        float rs0 = 0.0f, rs1 = 0.0f;
#pragma unroll
        for (int j = 0; j < 8; j++) {
            S[j][0] = __expf(S[j][0] - mn0);
            S[j][1] = __expf(S[j][1] - mn0);
            S[j][2] = __expf(S[j][2] - mn1);
            S[j][3] = __expf(S[j][3] - mn1);
            rs0 += S[j][0] + S[j][1];
            rs1 += S[j][2] + S[j][3];
        }
        rs0 += __shfl_xor_sync(0xffffffffu, rs0, 1);
        rs0 += __shfl_xor_sync(0xffffffffu, rs0, 2);
        rs1 += __shfl_xor_sync(0xffffffffu, rs1, 1);
        rs1 += __shfl_xor_sync(0xffffffffu, rs1, 2);
        l0 = l0 * alpha0 + rs0;
        l1 = l1 * alpha1 + rs1;
#pragma unroll
        for (int j = 0; j < 4; j++) {
            O[j][0] *= alpha0; O[j][1] *= alpha0;
            O[j][2] *= alpha1; O[j][3] *= alpha1;
        }
        __syncthreads();   // bias reads done before P overwrite
        // store P (tf32 bits)
#pragma unroll
        for (int j = 0; j < 8; j++) {
            int r = w * 16 + g;
            uint2 p0 = make_uint2(tf32_rna(S[j][0]), tf32_rna(S[j][1]));
            uint2 p1 = make_uint2(tf32_rna(S[j][2]), tf32_rna(S[j][3]));
            *(uint2*)(BPu + r * 68 + j * 8 + tg * 2) = p0;
            *(uint2*)(BPu + (r + 8) * 68 + j * 8 + tg * 2) = p1;
        }
        __syncthreads();
        // P @ V (TF32 1x)
        const unsigned* Vb = Vs + s * 2304;
#pragma unroll
        for (int kt = 0; kt < 8; kt++) {
            int kc = kt * 8 + tg;
            int r = w * 16 + g;
            unsigned a[4] = {BPu[r * 68 + kc], BPu[(r + 8) * 68 + kc],
                             BPu[r * 68 + kc + 4], BPu[(r + 8) * 68 + kc + 4]};
#pragma unroll
            for (int j = 0; j < 4; j++) {
                unsigned bb[2] = {Vb[kc * 36 + j * 8 + g], Vb[(kc + 4) * 36 + j * 8 + g]};
                mma8(O[j], a, bb);
            }
        }
    }
    // epilogue: write pre-split attn output for proj GEMM
    float inv0 = 1.0f / l0, inv1 = 1.0f / l1;
    int q0r = qt * 128 + w * 16 + g;
    size_t ob = ((size_t)b * NTOK + q0r) * DIMC + h * HD;
#pragma unroll
    for (int j = 0; j < 4; j++) {
        unsigned h0, l0u, h1, l1u;
        tf32_split(O[j][0] * inv0, h0, l0u);
        tf32_split(O[j][1] * inv0, h1, l1u);
        *(uint2*)(g_oh + ob + j * 8 + tg * 2) = make_uint2(h0, h1);
        *(uint2*)(g_ol + ob + j * 8 + tg * 2) = make_uint2(l0u, l1u);
        tf32_split(O[j][2] * inv1, h0, l0u);
        tf32_split(O[j][3] * inv1, h1, l1u);
        *(uint2*)(g_oh + ob + 8 * DIMC + j * 8 + tg * 2) = make_uint2(h0, h1);
        *(uint2*)(g_ol + ob + 8 * DIMC + j * 8 + tg * 2) = make_uint2(l0u, l1u);
    }
}

// ---------------- launcher ---------------------------------------------------
extern "C" void kernel_launch(void* const* d_in, const int* in_sizes, int n_in,
                              void* d_out, int out_size) {
    const float* x      = (const float*)d_in[0];
    const int*   rpi    = (const int*)d_in[3];
    const float* table  = (const float*)d_in[4];
    const float* qkv_w  = (const float*)d_in[5];
    const float* qkv_b  = (const float*)d_in[6];
    const float* proj_w = (const float*)d_in[7];
    const float* proj_b = (const float*)d_in[8];
    const float* temp   = (const float*)d_in[9];
    const float* qe     = (const float*)d_in[10];
    const float* fc1w   = (const float*)d_in[11];
    const float* fc1b   = (const float*)d_in[12];
    const float* fc2w   = (const float*)d_in[13];
    const float* fc2b   = (const float*)d_in[14];
    float* out = (float*)d_out;

    float* p_qkv;  cudaGetSymbolAddress((void**)&p_qkv,  g_qkv);
    unsigned* p_wh; cudaGetSymbolAddress((void**)&p_wh, g_wh);
    unsigned* p_wl; cudaGetSymbolAddress((void**)&p_wl, g_wl);
    unsigned* p_xh; cudaGetSymbolAddress((void**)&p_xh, g_xh);
    unsigned* p_xl; cudaGetSymbolAddress((void**)&p_xl, g_xl);
    unsigned* p_oh; cudaGetSymbolAddress((void**)&p_oh, g_oh);
    unsigned* p_ol; cudaGetSymbolAddress((void**)&p_ol, g_ol);

    static int attr_set = 0;
    if (!attr_set) {
        cudaFuncSetAttribute(attn4_kernel, cudaFuncAttributeMaxDynamicSharedMemorySize,
                             ATTN_SMEM);
        cudaFuncSetAttribute(gemm3s, cudaFuncAttributeMaxDynamicSharedMemorySize,
                             GEMM_SMEM);
        attr_set = 1;
    }

    scale_kernel<<<1, 32>>>(temp);
    wsplit_kernel<<<(4 * DIMC * DIMC + 255) / 256, 256>>>(qkv_w, proj_w);
    xsplit_kernel<<<(BATCH * NTOK * DIMC / 4) / 256, 256>>>(x);
    cpb_kernel<<<TABLE_SZ, 512>>>(table, fc1w, fc1b, fc2w, fc2b);
    bias_kernel<<<NTOK, 256>>>(rpi);
    {
        dim3 grid(3 * DIMC / 128, BATCH * NTOK / 128);
        gemm3s<<<grid, 256, GEMM_SMEM>>>(p_xh, p_xl, p_wh, p_wl, qkv_b, p_qkv,
                                         BATCH * NTOK, 3 * DIMC, DIMC);
    }
    reorg_kernel<<<BATCH * NTOK * NH / 8, 256>>>(qe);
    {
        dim3 grid(BATCH, NTOK / 128, NH);
        attn4_kernel<<<grid, 256, ATTN_SMEM>>>();
    }
    {
        dim3 grid(DIMC / 128, BATCH * NTOK / 128);
        gemm3s<<<grid, 256, GEMM_SMEM>>>(p_oh, p_ol, p_wh + 3 * DIMC * DIMC,
                                         p_wl + 3 * DIMC * DIMC, proj_b, out,
                                         BATCH * NTOK, DIMC, DIMC);
    }
}

// round 5
// speedup vs baseline: 1.3931x; 1.3931x over previous
#include <cuda_runtime.h>
#include <cuda_bf16.h>
#include <math.h>

// Problem constants
#define BATCH 8
#define NTOK 1024
#define DIMC 512
#define NH 16
#define HD 32
#define TABLE_SZ 3969
#define SEQ_SCALE 6.93147180559945309f  // ln(1024)

// ---------------- scratch (device globals; no allocation allowed) -------------
__device__ float g_scale[NH];
__device__ float g_t[TABLE_SZ * NH];
__device__ float g_bias[NH * NTOK * NTOK];              // [h][n][m] 64MB
__device__ float g_qkv[BATCH * NTOK * 3 * DIMC];        // 50MB
__device__ unsigned g_qh[BATCH * NH * NTOK * HD / 2];   // q hi, packed bf16 pairs
__device__ unsigned g_ql[BATCH * NH * NTOK * HD / 2];   // q lo
__device__ unsigned g_kh[BATCH * NH * NTOK * HD / 2];   // k hi
__device__ unsigned g_kl[BATCH * NH * NTOK * HD / 2];   // k lo
__device__ unsigned g_vt[BATCH * NH * NTOK * HD];       // v tf32
__device__ unsigned g_oh[BATCH * NTOK * DIMC / 2];      // attn out hi (bf16 pairs)
__device__ unsigned g_ol[BATCH * NTOK * DIMC / 2];      // attn out lo
__device__ unsigned g_xh[BATCH * NTOK * DIMC / 2];      // x hi
__device__ unsigned g_xl[BATCH * NTOK * DIMC / 2];      // x lo
__device__ unsigned g_wh[(3 * DIMC + DIMC) * DIMC / 2]; // W hi (qkv then proj)
__device__ unsigned g_wl[(3 * DIMC + DIMC) * DIMC / 2]; // W lo

// ---------------- helpers -----------------------------------------------------
__device__ __forceinline__ unsigned tf32_rna(float x) {
    unsigned r; asm("cvt.rna.tf32.f32 %0, %1;" : "=r"(r) : "f"(x)); return r;
}
// split pair (e=even k, o=odd k) into packed bf16 hi/lo words (e in low half)
__device__ __forceinline__ void bf16_split2(float e, float o, unsigned& hi, unsigned& lo) {
    __nv_bfloat162 h2 = __floats2bfloat162_rn(e, o);
    hi = *(unsigned*)&h2;
    float re = e - __bfloat162float(h2.x);
    float ro = o - __bfloat162float(h2.y);
    __nv_bfloat162 l2 = __floats2bfloat162_rn(re, ro);
    lo = *(unsigned*)&l2;
}
__device__ __forceinline__ void mma16(float* c, const unsigned* a, const unsigned* b) {
    asm volatile("mma.sync.aligned.m16n8k16.row.col.f32.bf16.bf16.f32 "
                 "{%0,%1,%2,%3}, {%4,%5,%6,%7}, {%8,%9}, {%0,%1,%2,%3};"
                 : "+f"(c[0]), "+f"(c[1]), "+f"(c[2]), "+f"(c[3])
                 : "r"(a[0]), "r"(a[1]), "r"(a[2]), "r"(a[3]),
                   "r"(b[0]), "r"(b[1]));
}
__device__ __forceinline__ void mma8t(float* c, const unsigned* a, const unsigned* b) {
    asm volatile("mma.sync.aligned.m16n8k8.row.col.f32.tf32.tf32.f32 "
                 "{%0,%1,%2,%3}, {%4,%5,%6,%7}, {%8,%9}, {%0,%1,%2,%3};"
                 : "+f"(c[0]), "+f"(c[1]), "+f"(c[2]), "+f"(c[3])
                 : "r"(a[0]), "r"(a[1]), "r"(a[2]), "r"(a[3]),
                   "r"(b[0]), "r"(b[1]));
}
__device__ __forceinline__ void cp16(void* sdst, const void* gsrc) {
    unsigned u = (unsigned)__cvta_generic_to_shared(sdst);
    asm volatile("cp.async.ca.shared.global [%0], [%1], 16;" :: "r"(u), "l"(gsrc));
}
#define CP_COMMIT() asm volatile("cp.async.commit_group;")
#define CP_WAIT(n)  asm volatile("cp.async.wait_group %0;" :: "n"(n))

// ---------------- kernel 1: scale = softplus(temperature) * ln(N) ------------
__global__ void scale_kernel(const float* __restrict__ temp) {
    int h = threadIdx.x;
    if (h < NH) {
        float t = temp[h];
        float sp = (t > 20.0f) ? t : log1pf(expf(t));
        g_scale[h] = sp * SEQ_SCALE;
    }
}

// ---------------- pre-split weights (bf16 pairs) -------------------------------
__global__ void wsplit_kernel(const float* __restrict__ qkvw,
                              const float* __restrict__ projw) {
    int i = blockIdx.x * 256 + threadIdx.x;   // pair index
    int nq2 = 3 * DIMC * DIMC / 2;
    float2 v;
    if (i < nq2) v = ((const float2*)qkvw)[i];
    else         v = ((const float2*)projw)[i - nq2];
    unsigned h, l;
    bf16_split2(v.x, v.y, h, l);
    g_wh[i] = h; g_wl[i] = l;
}

// ---------------- pre-split x (bf16 pairs) -------------------------------------
__global__ void xsplit_kernel(const float* __restrict__ x) {
    int i = blockIdx.x * 256 + threadIdx.x;   // pair index
    float2 v = ((const float2*)x)[i];
    unsigned h, l;
    bf16_split2(v.x, v.y, h, l);
    g_xh[i] = h; g_xl[i] = l;
}

// ---------------- kernel 2: CPB MLP  t[r][h] ---------------------------------
__global__ void cpb_kernel(const float* __restrict__ table,
                           const float* __restrict__ fc1w,
                           const float* __restrict__ fc1b,
                           const float* __restrict__ fc2w,
                           const float* __restrict__ fc2b) {
    __shared__ float hid[512];
    int r = blockIdx.x;
    int j = threadIdx.x;
    float c0 = table[r * 2 + 0];
    float c1 = table[r * 2 + 1];
    float hv = c0 * fc1w[j * 2 + 0] + c1 * fc1w[j * 2 + 1] + fc1b[j];
    hid[j] = fmaxf(hv, 0.0f);
    __syncthreads();
    int w = j >> 5;
    int lane = j & 31;
    float acc = 0.0f;
#pragma unroll
    for (int kk = lane; kk < 512; kk += 32) acc += hid[kk] * fc2w[w * 512 + kk];
#pragma unroll
    for (int off = 16; off >= 1; off >>= 1) acc += __shfl_xor_sync(0xffffffffu, acc, off);
    if (lane == 0) g_t[r * NH + w] = acc + fc2b[w];
}

// ---------------- kernel 3: bias gather  bias[h][n][m] = t[rpi[n][m]][h] -----
__global__ void bias_kernel(const int* __restrict__ rpi) {
    int n = blockIdx.x;
    for (int m = threadIdx.x; m < NTOK; m += blockDim.x) {
        int idx = rpi[n * NTOK + m];
        const float4* tp = (const float4*)(g_t + idx * NH);
        float4 t0 = tp[0], t1 = tp[1], t2 = tp[2], t3 = tp[3];
        float v[16] = {t0.x, t0.y, t0.z, t0.w, t1.x, t1.y, t1.z, t1.w,
                       t2.x, t2.y, t2.z, t2.w, t3.x, t3.y, t3.z, t3.w};
#pragma unroll
        for (int h = 0; h < NH; h++)
            g_bias[(h * NTOK + n) * NTOK + m] = v[h];
    }
}

// ---------------- 3xBF16 GEMM, cp.async 2-stage --------------------------------
// BM=BN=128, BK=32 floats (16 u32 pairs), 256 threads, 8 warps 4x2, warp 32x64.
// dyn smem: Ahs/Als/Whs/Wls each [2][128][20] u32  (16 used + 4 pad)
#define GEMM_SMEM (4 * 2 * 128 * 20 * 4)
__global__ __launch_bounds__(256, 2) void gemm3b(const unsigned* __restrict__ Ah,
                                                 const unsigned* __restrict__ Al,
                                                 const unsigned* __restrict__ Wh,
                                                 const unsigned* __restrict__ Wl,
                                                 const float* __restrict__ bias,
                                                 float* __restrict__ C,
                                                 int M, int Nn, int K) {
    extern __shared__ unsigned smg[];
    unsigned* Ahs = smg;               // [2][2560]
    unsigned* Als = smg + 2 * 2560;
    unsigned* Whs = smg + 4 * 2560;
    unsigned* Wls = smg + 6 * 2560;

    int tid = threadIdx.x;
    int wid = tid >> 5, lane = tid & 31;
    int g = lane >> 2, tg = lane & 3;
    int wm = wid & 3, wn = wid >> 2;
    int m0 = blockIdx.y * 128, n0 = blockIdx.x * 128;
    int KU = K >> 1;                   // u32 pairs per row

    int lrow = tid >> 2, lch = (tid & 3) * 4;   // rows 0..63, +64

    float acc[2][8][4];
#pragma unroll
    for (int mi = 0; mi < 2; mi++)
#pragma unroll
        for (int j = 0; j < 8; j++)
#pragma unroll
            for (int c = 0; c < 4; c++) acc[mi][j][c] = 0.0f;

    int nk = K >> 5;                   // BK=32 floats = 16 u32
#define G_LOAD(stage, ku0)                                                        \
    do {                                                                          \
        cp16(&Ahs[(stage) * 2560 + lrow * 20 + lch], Ah + (size_t)(m0 + lrow) * KU + (ku0) + lch);          \
        cp16(&Ahs[(stage) * 2560 + (lrow + 64) * 20 + lch], Ah + (size_t)(m0 + lrow + 64) * KU + (ku0) + lch); \
        cp16(&Als[(stage) * 2560 + lrow * 20 + lch], Al + (size_t)(m0 + lrow) * KU + (ku0) + lch);          \
        cp16(&Als[(stage) * 2560 + (lrow + 64) * 20 + lch], Al + (size_t)(m0 + lrow + 64) * KU + (ku0) + lch); \
        cp16(&Whs[(stage) * 2560 + lrow * 20 + lch], Wh + (size_t)(n0 + lrow) * KU + (ku0) + lch);          \
        cp16(&Whs[(stage) * 2560 + (lrow + 64) * 20 + lch], Wh + (size_t)(n0 + lrow + 64) * KU + (ku0) + lch); \
        cp16(&Wls[(stage) * 2560 + lrow * 20 + lch], Wl + (size_t)(n0 + lrow) * KU + (ku0) + lch);          \
        cp16(&Wls[(stage) * 2560 + (lrow + 64) * 20 + lch], Wl + (size_t)(n0 + lrow + 64) * KU + (ku0) + lch); \
        CP_COMMIT();                                                              \
    } while (0)

    G_LOAD(0, 0);

    for (int i = 0; i < nk; i++) {
        if (i + 1 < nk) {
            G_LOAD((i + 1) & 1, (i + 1) << 4);
            CP_WAIT(1);
        } else {
            CP_WAIT(0);
        }
        __syncthreads();
        int s = i & 1;
        const unsigned* Ahb = Ahs + s * 2560;
        const unsigned* Alb = Als + s * 2560;
        const unsigned* Whb = Whs + s * 2560;
        const unsigned* Wlb = Wls + s * 2560;
#pragma unroll
        for (int kt = 0; kt < 2; kt++) {
            int kc = kt * 8 + tg;
            unsigned ah[2][4], al[2][4];
#pragma unroll
            for (int mi = 0; mi < 2; mi++) {
                int r = wm * 32 + mi * 16 + g;
                ah[mi][0] = Ahb[r * 20 + kc];           al[mi][0] = Alb[r * 20 + kc];
                ah[mi][1] = Ahb[(r + 8) * 20 + kc];     al[mi][1] = Alb[(r + 8) * 20 + kc];
                ah[mi][2] = Ahb[r * 20 + kc + 4];       al[mi][2] = Alb[r * 20 + kc + 4];
                ah[mi][3] = Ahb[(r + 8) * 20 + kc + 4]; al[mi][3] = Alb[(r + 8) * 20 + kc + 4];
            }
#pragma unroll
            for (int j = 0; j < 8; j++) {
                int col = wn * 64 + j * 8 + g;
                unsigned bh[2] = {Whb[col * 20 + kc], Whb[col * 20 + kc + 4]};
                unsigned bl[2] = {Wlb[col * 20 + kc], Wlb[col * 20 + kc + 4]};
#pragma unroll
                for (int mi = 0; mi < 2; mi++) {
                    mma16(acc[mi][j], ah[mi], bh);
                    mma16(acc[mi][j], ah[mi], bl);
                    mma16(acc[mi][j], al[mi], bh);
                }
            }
        }
        __syncthreads();
    }
    // epilogue: fp32 + bias
#pragma unroll
    for (int j = 0; j < 8; j++) {
        int col = n0 + wn * 64 + j * 8 + tg * 2;
        float2 bv = *(const float2*)(bias + col);
#pragma unroll
        for (int mi = 0; mi < 2; mi++) {
            int row = m0 + wm * 32 + mi * 16 + g;
            float2 o0 = make_float2(acc[mi][j][0] + bv.x, acc[mi][j][1] + bv.y);
            float2 o1 = make_float2(acc[mi][j][2] + bv.x, acc[mi][j][3] + bv.y);
            *(float2*)(C + (size_t)row * Nn + col) = o0;
            *(float2*)(C + (size_t)(row + 8) * Nn + col) = o1;
        }
    }
}

// ---------------- reorg: normalize q/k, bf16-split+pack, v tf32 ----------------
__global__ void reorg_kernel(const float* __restrict__ qe) {
    int wg = blockIdx.x * 8 + (threadIdx.x >> 5);
    int lane = threadIdx.x & 31;
    int h = wg & 15;
    int bn = wg >> 4;
    int b = bn >> 10;
    int n = bn & 1023;
    const float* base = g_qkv + (size_t)bn * (3 * DIMC);
    float q = base[h * HD + lane];
    float k = base[DIMC + h * HD + lane];
    float v = base[2 * DIMC + h * HD + lane];

    float s = q * q;
#pragma unroll
    for (int off = 16; off >= 1; off >>= 1) s += __shfl_xor_sync(0xffffffffu, s, off);
    float qn = q / fmaxf(sqrtf(s), 1e-12f);
    qn = (qn + qe[h * HD + lane]) * g_scale[h];

    s = k * k;
#pragma unroll
    for (int off = 16; off >= 1; off >>= 1) s += __shfl_xor_sync(0xffffffffu, s, off);
    float kn = k / fmaxf(sqrtf(s), 1e-12f);

    // bf16 hi/lo of my element
    __nv_bfloat16 qbh = __float2bfloat16_rn(qn);
    unsigned qhu = (unsigned)__bfloat16_as_ushort(qbh);
    unsigned qlu = (unsigned)__bfloat16_as_ushort(__float2bfloat16_rn(qn - __bfloat162float(qbh)));
    __nv_bfloat16 kbh = __float2bfloat16_rn(kn);
    unsigned khu = (unsigned)__bfloat16_as_ushort(kbh);
    unsigned klu = (unsigned)__bfloat16_as_ushort(__float2bfloat16_rn(kn - __bfloat162float(kbh)));

    unsigned qho = __shfl_down_sync(0xffffffffu, qhu, 1);
    unsigned qlo = __shfl_down_sync(0xffffffffu, qlu, 1);
    unsigned kho = __shfl_down_sync(0xffffffffu, khu, 1);
    unsigned klo = __shfl_down_sync(0xffffffffu, klu, 1);

    size_t rbase = ((size_t)(b * NH + h) * NTOK + n) * (HD / 2);
    if ((lane & 1) == 0) {
        int c = lane >> 1;
        g_qh[rbase + c] = qhu | (qho << 16);
        g_ql[rbase + c] = qlu | (qlo << 16);
        g_kh[rbase + c] = khu | (kho << 16);
        g_kl[rbase + c] = klu | (klo << 16);
    }
    g_vt[((size_t)(b * NH + h) * NTOK + n) * HD + lane] = tf32_rna(v);
}

// ---------------- attention v5: 3xBF16 QK, tf32 PV, 3-sync pipeline ------------
// grid (B, N/128, H), 256 threads, 128 queries/block, key tiles 64.
// smem: Khs[2][64][20], Kls[2][64][20], Vs[2][64][36] u32, BB[128][68] f32, Pb[128][68] u32
#define ATTN_SMEM ((2 * 1280 * 2 + 2 * 2304 + 8704 + 8704) * 4)
__global__ __launch_bounds__(256, 2) void attn5_kernel() {
    extern __shared__ unsigned smu[];
    unsigned* Khs = smu;                    // [2][1280]
    unsigned* Kls = smu + 2560;
    unsigned* Vs  = smu + 5120;             // [2][2304]
    float* BB = (float*)(smu + 5120 + 4608);     // [128][68]
    unsigned* Pb = smu + 5120 + 4608 + 8704;     // [128][68]

    int b = blockIdx.x, qt = blockIdx.y, h = blockIdx.z;
    int tid = threadIdx.x;
    int w = tid >> 5, lane = tid & 31;
    int g = lane >> 2, tg = lane & 3;

    size_t bh16 = (size_t)(b * NH + h) * NTOK * (HD / 2);
    const unsigned* qhb = g_qh + bh16 + (size_t)qt * 128 * (HD / 2);
    const unsigned* qlb = g_ql + bh16 + (size_t)qt * 128 * (HD / 2);
    const unsigned* khb = g_kh + bh16;
    const unsigned* klb = g_kl + bh16;
    const unsigned* vtb = g_vt + (size_t)(b * NH + h) * NTOK * HD;
    const float* bbase = g_bias + ((size_t)h * NTOK + qt * 128) * NTOK;

    int krow = tid >> 2, kch = (tid & 3) * 4;   // K loaders (64 rows x 16 u32)
    int vrow = tid >> 3, vch = (tid & 7) * 4;   // V loaders (64 rows x 32 u32)
#define KV_LOAD(stage, mt_)                                                       \
    do {                                                                          \
        cp16(&Khs[(stage) * 1280 + krow * 20 + kch], khb + (size_t)((mt_) * 64 + krow) * 16 + kch); \
        cp16(&Kls[(stage) * 1280 + krow * 20 + kch], klb + (size_t)((mt_) * 64 + krow) * 16 + kch); \
        cp16(&Vs[(stage) * 2304 + vrow * 36 + vch], vtb + (size_t)((mt_) * 64 + vrow) * 32 + vch);  \
        cp16(&Vs[(stage) * 2304 + (vrow + 32) * 36 + vch], vtb + (size_t)((mt_) * 64 + vrow + 32) * 32 + vch); \
        CP_COMMIT();                                                              \
    } while (0)

    KV_LOAD(0, 0);

    // Q fragments (bf16 pairs, persist in registers)
    unsigned Qh[2][4], Ql[2][4];
    int r = w * 16 + g;
#pragma unroll
    for (int kt = 0; kt < 2; kt++) {
        int c = kt * 8 + tg;
        Qh[kt][0] = qhb[r * 16 + c];           Ql[kt][0] = qlb[r * 16 + c];
        Qh[kt][1] = qhb[(r + 8) * 16 + c];     Ql[kt][1] = qlb[(r + 8) * 16 + c];
        Qh[kt][2] = qhb[r * 16 + c + 4];       Ql[kt][2] = qlb[r * 16 + c + 4];
        Qh[kt][3] = qhb[(r + 8) * 16 + c + 4]; Ql[kt][3] = qlb[(r + 8) * 16 + c + 4];
    }

    float m0 = -INFINITY, m1 = -INFINITY, l0 = 0.0f, l1 = 0.0f;
    float O[4][4];
#pragma unroll
    for (int j = 0; j < 4; j++)
#pragma unroll
        for (int c = 0; c < 4; c++) O[j][c] = 0.0f;

    for (int mt = 0; mt < 16; mt++) {
        int s = mt & 1;
        CP_WAIT(0);        // KV(mt) landed (only group in flight)
        __syncthreads();   // KV visible; bias buffer free; P(prev) consumed
        // bias(mt) cp.async — its own group, flies during QK
#pragma unroll
        for (int p = 0; p < 8; p++) {
            int c = tid + 256 * p;
            int row = c >> 4, ch = (c & 15) * 4;
            cp16(&BB[row * 68 + ch], bbase + (size_t)row * NTOK + mt * 64 + ch);
        }
        CP_COMMIT();
        if (mt + 1 < 16) KV_LOAD(s ^ 1, mt + 1);

        // QK^T: 3xBF16
        float S[8][4];
#pragma unroll
        for (int j = 0; j < 8; j++)
#pragma unroll
            for (int c = 0; c < 4; c++) S[j][c] = 0.0f;
        const unsigned* Khb = Khs + s * 1280;
        const unsigned* Klb = Kls + s * 1280;
#pragma unroll
        for (int kt = 0; kt < 2; kt++) {
            int kc = kt * 8 + tg;
#pragma unroll
            for (int j = 0; j < 8; j++) {
                int key = j * 8 + g;
                unsigned bh2[2] = {Khb[key * 20 + kc], Khb[key * 20 + kc + 4]};
                unsigned bl2[2] = {Klb[key * 20 + kc], Klb[key * 20 + kc + 4]};
                mma16(S[j], Qh[kt], bh2);
                mma16(S[j], Qh[kt], bl2);
                mma16(S[j], Ql[kt], bh2);
            }
        }
        if (mt + 1 < 16) { CP_WAIT(1); } else { CP_WAIT(0); }
        __syncthreads();   // bias visible
        // bias add
#pragma unroll
        for (int j = 0; j < 8; j++) {
            float2 b0 = *(const float2*)(BB + r * 68 + j * 8 + tg * 2);
            float2 b1 = *(const float2*)(BB + (r + 8) * 68 + j * 8 + tg * 2);
            S[j][0] += b0.x; S[j][1] += b0.y;
            S[j][2] += b1.x; S[j][3] += b1.y;
        }
        // online softmax
        float mx0 = -INFINITY, mx1 = -INFINITY;
#pragma unroll
        for (int j = 0; j < 8; j++) {
            mx0 = fmaxf(mx0, fmaxf(S[j][0], S[j][1]));
            mx1 = fmaxf(mx1, fmaxf(S[j][2], S[j][3]));
        }
        mx0 = fmaxf(mx0, __shfl_xor_sync(0xffffffffu, mx0, 1));
        mx0 = fmaxf(mx0, __shfl_xor_sync(0xffffffffu, mx0, 2));
        mx1 = fmaxf(mx1, __shfl_xor_sync(0xffffffffu, mx1, 1));
        mx1 = fmaxf(mx1, __shfl_xor_sync(0xffffffffu, mx1, 2));
        float mn0 = fmaxf(m0, mx0), mn1 = fmaxf(m1, mx1);
        float alpha0 = __expf(m0 - mn0), alpha1 = __expf(m1 - mn1);
        m0 = mn0; m1 = mn1;
        float rs0 = 0.0f, rs1 = 0.0f;
#pragma unroll
        for (int j = 0; j < 8; j++) {
            S[j][0] = __expf(S[j][0] - mn0);
            S[j][1] = __expf(S[j][1] - mn0);
            S[j][2] = __expf(S[j][2] - mn1);
            S[j][3] = __expf(S[j][3] - mn1);
            rs0 += S[j][0] + S[j][1];
            rs1 += S[j][2] + S[j][3];
        }
        rs0 += __shfl_xor_sync(0xffffffffu, rs0, 1);
        rs0 += __shfl_xor_sync(0xffffffffu, rs0, 2);
        rs1 += __shfl_xor_sync(0xffffffffu, rs1, 1);
        rs1 += __shfl_xor_sync(0xffffffffu, rs1, 2);
        l0 = l0 * alpha0 + rs0;
        l1 = l1 * alpha1 + rs1;
#pragma unroll
        for (int j = 0; j < 4; j++) {
            O[j][0] *= alpha0; O[j][1] *= alpha0;
            O[j][2] *= alpha1; O[j][3] *= alpha1;
        }
        // store P (tf32 bits) into dedicated buffer
#pragma unroll
        for (int j = 0; j < 8; j++) {
            uint2 p0 = make_uint2(tf32_rna(S[j][0]), tf32_rna(S[j][1]));
            uint2 p1 = make_uint2(tf32_rna(S[j][2]), tf32_rna(S[j][3]));
            *(uint2*)(Pb + r * 68 + j * 8 + tg * 2) = p0;
            *(uint2*)(Pb + (r + 8) * 68 + j * 8 + tg * 2) = p1;
        }
        __syncthreads();   // P visible
        // P @ V (TF32 1x)
        const unsigned* Vb = Vs + s * 2304;
#pragma unroll
        for (int kt = 0; kt < 8; kt++) {
            int kc = kt * 8 + tg;
            unsigned a[4] = {Pb[r * 68 + kc], Pb[(r + 8) * 68 + kc],
                             Pb[r * 68 + kc + 4], Pb[(r + 8) * 68 + kc + 4]};
#pragma unroll
            for (int j = 0; j < 4; j++) {
                unsigned bb[2] = {Vb[kc * 36 + j * 8 + g], Vb[(kc + 4) * 36 + j * 8 + g]};
                mma8t(O[j], a, bb);
            }
        }
    }
    // epilogue: pack bf16 hi/lo pairs for proj GEMM
    float inv0 = 1.0f / l0, inv1 = 1.0f / l1;
    int q0r = qt * 128 + w * 16 + g;
    size_t row0 = (size_t)b * NTOK + q0r;
    int colbase = h * 16;
#pragma unroll
    for (int j = 0; j < 4; j++) {
        unsigned hw, lw;
        bf16_split2(O[j][0] * inv0, O[j][1] * inv0, hw, lw);
        g_oh[row0 * 256 + colbase + j * 4 + tg] = hw;
        g_ol[row0 * 256 + colbase + j * 4 + tg] = lw;
        bf16_split2(O[j][2] * inv1, O[j][3] * inv1, hw, lw);
        g_oh[(row0 + 8) * 256 + colbase + j * 4 + tg] = hw;
        g_ol[(row0 + 8) * 256 + colbase + j * 4 + tg] = lw;
    }
}

// ---------------- launcher ---------------------------------------------------
extern "C" void kernel_launch(void* const* d_in, const int* in_sizes, int n_in,
                              void* d_out, int out_size) {
    const float* x      = (const float*)d_in[0];
    const int*   rpi    = (const int*)d_in[3];
    const float* table  = (const float*)d_in[4];
    const float* qkv_w  = (const float*)d_in[5];
    const float* qkv_b  = (const float*)d_in[6];
    const float* proj_w = (const float*)d_in[7];
    const float* proj_b = (const float*)d_in[8];
    const float* temp   = (const float*)d_in[9];
    const float* qe     = (const float*)d_in[10];
    const float* fc1w   = (const float*)d_in[11];
    const float* fc1b   = (const float*)d_in[12];
    const float* fc2w   = (const float*)d_in[13];
    const float* fc2b   = (const float*)d_in[14];
    float* out = (float*)d_out;

    float* p_qkv;  cudaGetSymbolAddress((void**)&p_qkv,  g_qkv);
    unsigned* p_wh; cudaGetSymbolAddress((void**)&p_wh, g_wh);
    unsigned* p_wl; cudaGetSymbolAddress((void**)&p_wl, g_wl);
    unsigned* p_xh; cudaGetSymbolAddress((void**)&p_xh, g_xh);
    unsigned* p_xl; cudaGetSymbolAddress((void**)&p_xl, g_xl);
    unsigned* p_oh; cudaGetSymbolAddress((void**)&p_oh, g_oh);
    unsigned* p_ol; cudaGetSymbolAddress((void**)&p_ol, g_ol);

    static int attr_set = 0;
    if (!attr_set) {
        cudaFuncSetAttribute(attn5_kernel, cudaFuncAttributeMaxDynamicSharedMemorySize,
                             ATTN_SMEM);
        cudaFuncSetAttribute(gemm3b, cudaFuncAttributeMaxDynamicSharedMemorySize,
                             GEMM_SMEM);
        attr_set = 1;
    }

    scale_kernel<<<1, 32>>>(temp);
    wsplit_kernel<<<4 * DIMC * DIMC / 2 / 256, 256>>>(qkv_w, proj_w);
    xsplit_kernel<<<BATCH * NTOK * DIMC / 2 / 256, 256>>>(x);
    cpb_kernel<<<TABLE_SZ, 512>>>(table, fc1w, fc1b, fc2w, fc2b);
    bias_kernel<<<NTOK, 256>>>(rpi);
    {
        dim3 grid(3 * DIMC / 128, BATCH * NTOK / 128);
        gemm3b<<<grid, 256, GEMM_SMEM>>>(p_xh, p_xl, p_wh, p_wl, qkv_b, p_qkv,
                                         BATCH * NTOK, 3 * DIMC, DIMC);
    }
    reorg_kernel<<<BATCH * NTOK * NH / 8, 256>>>(qe);
    {
        dim3 grid(BATCH, NTOK / 128, NH);
        attn5_kernel<<<grid, 256, ATTN_SMEM>>>();
    }
    {
        dim3 grid(DIMC / 128, BATCH * NTOK / 128);
        gemm3b<<<grid, 256, GEMM_SMEM>>>(p_oh, p_ol, p_wh + 3 * DIMC * DIMC / 2,
                                         p_wl + 3 * DIMC * DIMC / 2, proj_b, out,
                                         BATCH * NTOK, DIMC, DIMC);
    }
}

// round 7
// speedup vs baseline: 1.5412x; 1.1063x over previous
#include <cuda_runtime.h>
#include <cuda_bf16.h>
#include <cuda_fp16.h>
#include <math.h>

// Problem constants
#define BATCH 8
#define NTOK 1024
#define DIMC 512
#define NH 16
#define HD 32
#define TABLE_SZ 3969
#define SEQ_SCALE 6.93147180559945309f  // ln(1024)

// ---------------- scratch (device globals; no allocation allowed) -------------
__device__ float g_scale[NH];
__device__ float g_t[TABLE_SZ * NH];
__device__ __half g_biash[NH * NTOK * NTOK];            // [h][n][m] 32MB fp16
__device__ float g_qkv[BATCH * NTOK * 3 * DIMC];        // 50MB
__device__ unsigned g_qh[BATCH * NH * NTOK * HD / 2];   // q hi, packed bf16 pairs
__device__ unsigned g_ql[BATCH * NH * NTOK * HD / 2];   // q lo
__device__ unsigned g_kh[BATCH * NH * NTOK * HD / 2];   // k hi
__device__ unsigned g_kl[BATCH * NH * NTOK * HD / 2];   // k lo
__device__ unsigned g_vt[BATCH * NH * NTOK * HD];       // v tf32
__device__ unsigned g_oh[BATCH * NTOK * DIMC / 2];      // attn out hi (bf16 pairs)
__device__ unsigned g_ol[BATCH * NTOK * DIMC / 2];      // attn out lo
__device__ unsigned g_xh[BATCH * NTOK * DIMC / 2];      // x hi
__device__ unsigned g_xl[BATCH * NTOK * DIMC / 2];      // x lo
__device__ unsigned g_wh[(3 * DIMC + DIMC) * DIMC / 2]; // W hi (qkv then proj)
__device__ unsigned g_wl[(3 * DIMC + DIMC) * DIMC / 2]; // W lo

// ---------------- helpers -----------------------------------------------------
__device__ __forceinline__ unsigned tf32_rna(float x) {
    unsigned r; asm("cvt.rna.tf32.f32 %0, %1;" : "=r"(r) : "f"(x)); return r;
}
// split pair (e=even k, o=odd k) into packed bf16 hi/lo words (e in low half)
__device__ __forceinline__ void bf16_split2(float e, float o, unsigned& hi, unsigned& lo) {
    __nv_bfloat162 h2 = __floats2bfloat162_rn(e, o);
    hi = *(unsigned*)&h2;
    float re = e - __bfloat162float(h2.x);
    float ro = o - __bfloat162float(h2.y);
    __nv_bfloat162 l2 = __floats2bfloat162_rn(re, ro);
    lo = *(unsigned*)&l2;
}
__device__ __forceinline__ void mma16(float* c, const unsigned* a, const unsigned* b) {
    asm volatile("mma.sync.aligned.m16n8k16.row.col.f32.bf16.bf16.f32 "
                 "{%0,%1,%2,%3}, {%4,%5,%6,%7}, {%8,%9}, {%0,%1,%2,%3};"
                 : "+f"(c[0]), "+f"(c[1]), "+f"(c[2]), "+f"(c[3])
                 : "r"(a[0]), "r"(a[1]), "r"(a[2]), "r"(a[3]),
                   "r"(b[0]), "r"(b[1]));
}
__device__ __forceinline__ void mma8t(float* c, const unsigned* a, const unsigned* b) {
    asm volatile("mma.sync.aligned.m16n8k8.row.col.f32.tf32.tf32.f32 "
                 "{%0,%1,%2,%3}, {%4,%5,%6,%7}, {%8,%9}, {%0,%1,%2,%3};"
                 : "+f"(c[0]), "+f"(c[1]), "+f"(c[2]), "+f"(c[3])
                 : "r"(a[0]), "r"(a[1]), "r"(a[2]), "r"(a[3]),
                   "r"(b[0]), "r"(b[1]));
}
__device__ __forceinline__ void cp16(void* sdst, const void* gsrc) {
    unsigned u = (unsigned)__cvta_generic_to_shared(sdst);
    asm volatile("cp.async.ca.shared.global [%0], [%1], 16;" :: "r"(u), "l"(gsrc));
}
#define CP_COMMIT() asm volatile("cp.async.commit_group;")
#define CP_WAIT(n)  asm volatile("cp.async.wait_group %0;" :: "n"(n))

// ---------------- fused split: weights + x (bf16 hi/lo pairs) ------------------
#define NW2 (4 * DIMC * DIMC / 2)       // 524288 weight pairs
#define NX2 (BATCH * NTOK * DIMC / 2)   // 2097152 x pairs
__global__ void split_kernel(const float* __restrict__ qkvw,
                             const float* __restrict__ projw,
                             const float* __restrict__ x) {
    int i = blockIdx.x * 256 + threadIdx.x;
    unsigned h, l;
    if (i < NW2) {
        int nq2 = 3 * DIMC * DIMC / 2;
        float2 v = (i < nq2) ? ((const float2*)qkvw)[i] : ((const float2*)projw)[i - nq2];
        bf16_split2(v.x, v.y, h, l);
        g_wh[i] = h; g_wl[i] = l;
    } else {
        int j = i - NW2;
        float2 v = ((const float2*)x)[j];
        bf16_split2(v.x, v.y, h, l);
        g_xh[j] = h; g_xl[j] = l;
    }
}

// ---------------- CPB MLP t[r][h] (+ fused temperature scale) -----------------
__global__ void cpb_kernel(const float* __restrict__ table,
                           const float* __restrict__ fc1w,
                           const float* __restrict__ fc1b,
                           const float* __restrict__ fc2w,
                           const float* __restrict__ fc2b,
                           const float* __restrict__ temp) {
    __shared__ float hid[512];
    int r = blockIdx.x;
    int j = threadIdx.x;
    if (r == 0 && j < NH) {
        float t = temp[j];
        float sp = (t > 20.0f) ? t : log1pf(expf(t));
        g_scale[j] = sp * SEQ_SCALE;
    }
    float c0 = table[r * 2 + 0];
    float c1 = table[r * 2 + 1];
    float hv = c0 * fc1w[j * 2 + 0] + c1 * fc1w[j * 2 + 1] + fc1b[j];
    hid[j] = fmaxf(hv, 0.0f);
    __syncthreads();
    int w = j >> 5;
    int lane = j & 31;
    float acc = 0.0f;
#pragma unroll
    for (int kk = lane; kk < 512; kk += 32) acc += hid[kk] * fc2w[w * 512 + kk];
#pragma unroll
    for (int off = 16; off >= 1; off >>= 1) acc += __shfl_xor_sync(0xffffffffu, acc, off);
    if (lane == 0) g_t[r * NH + w] = acc + fc2b[w];
}

// ---------------- bias gather  biash[h][n][m] = half(t[rpi[n][m]][h]) ---------
__global__ void bias_kernel(const int* __restrict__ rpi) {
    int n = blockIdx.x;
    for (int m = threadIdx.x; m < NTOK; m += blockDim.x) {
        int idx = rpi[n * NTOK + m];
        const float4* tp = (const float4*)(g_t + idx * NH);
        float4 t0 = tp[0], t1 = tp[1], t2 = tp[2], t3 = tp[3];
        float v[16] = {t0.x, t0.y, t0.z, t0.w, t1.x, t1.y, t1.z, t1.w,
                       t2.x, t2.y, t2.z, t2.w, t3.x, t3.y, t3.z, t3.w};
#pragma unroll
        for (int h = 0; h < NH; h++)
            g_biash[((size_t)h * NTOK + n) * NTOK + m] = __float2half(v[h]);
    }
}

// ---------------- 3xBF16 GEMM, cp.async 2-stage --------------------------------
#define GEMM_SMEM (4 * 2 * 128 * 20 * 4)
__global__ __launch_bounds__(256, 2) void gemm3b(const unsigned* __restrict__ Ah,
                                                 const unsigned* __restrict__ Al,
                                                 const unsigned* __restrict__ Wh,
                                                 const unsigned* __restrict__ Wl,
                                                 const float* __restrict__ bias,
                                                 float* __restrict__ C,
                                                 int M, int Nn, int K) {
    extern __shared__ unsigned smg[];
    unsigned* Ahs = smg;               // [2][2560]
    unsigned* Als = smg + 2 * 2560;
    unsigned* Whs = smg + 4 * 2560;
    unsigned* Wls = smg + 6 * 2560;

    int tid = threadIdx.x;
    int wid = tid >> 5, lane = tid & 31;
    int g = lane >> 2, tg = lane & 3;
    int wm = wid & 3, wn = wid >> 2;
    int m0 = blockIdx.y * 128, n0 = blockIdx.x * 128;
    int KU = K >> 1;

    int lrow = tid >> 2, lch = (tid & 3) * 4;

    float acc[2][8][4];
#pragma unroll
    for (int mi = 0; mi < 2; mi++)
#pragma unroll
        for (int j = 0; j < 8; j++)
#pragma unroll
            for (int c = 0; c < 4; c++) acc[mi][j][c] = 0.0f;

    int nk = K >> 5;
#define G_LOAD(stage, ku0)                                                        \
    do {                                                                          \
        cp16(&Ahs[(stage) * 2560 + lrow * 20 + lch], Ah + (size_t)(m0 + lrow) * KU + (ku0) + lch);          \
        cp16(&Ahs[(stage) * 2560 + (lrow + 64) * 20 + lch], Ah + (size_t)(m0 + lrow + 64) * KU + (ku0) + lch); \
        cp16(&Als[(stage) * 2560 + lrow * 20 + lch], Al + (size_t)(m0 + lrow) * KU + (ku0) + lch);          \
        cp16(&Als[(stage) * 2560 + (lrow + 64) * 20 + lch], Al + (size_t)(m0 + lrow + 64) * KU + (ku0) + lch); \
        cp16(&Whs[(stage) * 2560 + lrow * 20 + lch], Wh + (size_t)(n0 + lrow) * KU + (ku0) + lch);          \
        cp16(&Whs[(stage) * 2560 + (lrow + 64) * 20 + lch], Wh + (size_t)(n0 + lrow + 64) * KU + (ku0) + lch); \
        cp16(&Wls[(stage) * 2560 + lrow * 20 + lch], Wl + (size_t)(n0 + lrow) * KU + (ku0) + lch);          \
        cp16(&Wls[(stage) * 2560 + (lrow + 64) * 20 + lch], Wl + (size_t)(n0 + lrow + 64) * KU + (ku0) + lch); \
        CP_COMMIT();                                                              \
    } while (0)

    G_LOAD(0, 0);

    for (int i = 0; i < nk; i++) {
        if (i + 1 < nk) {
            G_LOAD((i + 1) & 1, (i + 1) << 4);
            CP_WAIT(1);
        } else {
            CP_WAIT(0);
        }
        __syncthreads();
        int s = i & 1;
        const unsigned* Ahb = Ahs + s * 2560;
        const unsigned* Alb = Als + s * 2560;
        const unsigned* Whb = Whs + s * 2560;
        const unsigned* Wlb = Wls + s * 2560;
#pragma unroll
        for (int kt = 0; kt < 2; kt++) {
            int kc = kt * 8 + tg;
            unsigned ah[2][4], al[2][4];
#pragma unroll
            for (int mi = 0; mi < 2; mi++) {
                int r = wm * 32 + mi * 16 + g;
                ah[mi][0] = Ahb[r * 20 + kc];           al[mi][0] = Alb[r * 20 + kc];
                ah[mi][1] = Ahb[(r + 8) * 20 + kc];     al[mi][1] = Alb[(r + 8) * 20 + kc];
                ah[mi][2] = Ahb[r * 20 + kc + 4];       al[mi][2] = Alb[r * 20 + kc + 4];
                ah[mi][3] = Ahb[(r + 8) * 20 + kc + 4]; al[mi][3] = Alb[(r + 8) * 20 + kc + 4];
            }
#pragma unroll
            for (int j = 0; j < 8; j++) {
                int col = wn * 64 + j * 8 + g;
                unsigned bh[2] = {Whb[col * 20 + kc], Whb[col * 20 + kc + 4]};
                unsigned bl[2] = {Wlb[col * 20 + kc], Wlb[col * 20 + kc + 4]};
#pragma unroll
                for (int mi = 0; mi < 2; mi++) {
                    mma16(acc[mi][j], ah[mi], bh);
                    mma16(acc[mi][j], ah[mi], bl);
                    mma16(acc[mi][j], al[mi], bh);
                }
            }
        }
        __syncthreads();
    }
#pragma unroll
    for (int j = 0; j < 8; j++) {
        int col = n0 + wn * 64 + j * 8 + tg * 2;
        float2 bv = *(const float2*)(bias + col);
#pragma unroll
        for (int mi = 0; mi < 2; mi++) {
            int row = m0 + wm * 32 + mi * 16 + g;
            float2 o0 = make_float2(acc[mi][j][0] + bv.x, acc[mi][j][1] + bv.y);
            float2 o1 = make_float2(acc[mi][j][2] + bv.x, acc[mi][j][3] + bv.y);
            *(float2*)(C + (size_t)row * Nn + col) = o0;
            *(float2*)(C + (size_t)(row + 8) * Nn + col) = o1;
        }
    }
}

// ---------------- reorg: normalize q/k, bf16-split+pack, v tf32 ----------------
__global__ void reorg_kernel(const float* __restrict__ qe) {
    int wg = blockIdx.x * 8 + (threadIdx.x >> 5);
    int lane = threadIdx.x & 31;
    int h = wg & 15;
    int bn = wg >> 4;
    int b = bn >> 10;
    int n = bn & 1023;
    const float* base = g_qkv + (size_t)bn * (3 * DIMC);
    float q = base[h * HD + lane];
    float k = base[DIMC + h * HD + lane];
    float v = base[2 * DIMC + h * HD + lane];

    float s = q * q;
#pragma unroll
    for (int off = 16; off >= 1; off >>= 1) s += __shfl_xor_sync(0xffffffffu, s, off);
    float qn = q / fmaxf(sqrtf(s), 1e-12f);
    qn = (qn + qe[h * HD + lane]) * g_scale[h];

    s = k * k;
#pragma unroll
    for (int off = 16; off >= 1; off >>= 1) s += __shfl_xor_sync(0xffffffffu, s, off);
    float kn = k / fmaxf(sqrtf(s), 1e-12f);

    __nv_bfloat16 qbh = __float2bfloat16_rn(qn);
    unsigned qhu = (unsigned)__bfloat16_as_ushort(qbh);
    unsigned qlu = (unsigned)__bfloat16_as_ushort(__float2bfloat16_rn(qn - __bfloat162float(qbh)));
    __nv_bfloat16 kbh = __float2bfloat16_rn(kn);
    unsigned khu = (unsigned)__bfloat16_as_ushort(kbh);
    unsigned klu = (unsigned)__bfloat16_as_ushort(__float2bfloat16_rn(kn - __bfloat162float(kbh)));

    unsigned qho = __shfl_down_sync(0xffffffffu, qhu, 1);
    unsigned qlo = __shfl_down_sync(0xffffffffu, qlu, 1);
    unsigned kho = __shfl_down_sync(0xffffffffu, khu, 1);
    unsigned klo = __shfl_down_sync(0xffffffffu, klu, 1);

    size_t rbase = ((size_t)(b * NH + h) * NTOK + n) * (HD / 2);
    if ((lane & 1) == 0) {
        int c = lane >> 1;
        g_qh[rbase + c] = qhu | (qho << 16);
        g_ql[rbase + c] = qlu | (qlo << 16);
        g_kh[rbase + c] = khu | (kho << 16);
        g_kl[rbase + c] = klu | (klo << 16);
    }
    g_vt[((size_t)(b * NH + h) * NTOK + n) * HD + lane] = tf32_rna(v);
}

// ---------------- attention v7: fp16 bias, safe 2-sync pipeline ----------------
// grid (B, N/128, H), 256 threads, 128 queries/block, key tiles 64.
// smem: Khs[2][64][20], Kls[2][64][20], Vs[2][64][36] u32,
//       BBh[2][128][72] half, Pb[128][68] u32
// Safety: KVB_LOAD(s^1, mt+1) is issued only AFTER the top __syncthreads(),
// which is the first barrier after all warps' PV(mt-1) reads of stage s^1.
#define ATTN_SMEM ((2560 + 2560 + 4608 + 9216 + 8704) * 4)
__global__ __launch_bounds__(256, 2) void attn7_kernel() {
    extern __shared__ unsigned smu[];
    unsigned* Khs = smu;                     // [2][1280]
    unsigned* Kls = smu + 2560;
    unsigned* Vs  = smu + 5120;              // [2][2304]
    __half*  BBh = (__half*)(smu + 9728);    // [2][128*72]
    unsigned* Pb = smu + 9728 + 9216;        // [128][68]

    int b = blockIdx.x, qt = blockIdx.y, h = blockIdx.z;
    int tid = threadIdx.x;
    int w = tid >> 5, lane = tid & 31;
    int g = lane >> 2, tg = lane & 3;

    size_t bh16 = (size_t)(b * NH + h) * NTOK * (HD / 2);
    const unsigned* qhb = g_qh + bh16 + (size_t)qt * 128 * (HD / 2);
    const unsigned* qlb = g_ql + bh16 + (size_t)qt * 128 * (HD / 2);
    const unsigned* khb = g_kh + bh16;
    const unsigned* klb = g_kl + bh16;
    const unsigned* vtb = g_vt + (size_t)(b * NH + h) * NTOK * HD;
    const __half* bbh = g_biash + ((size_t)h * NTOK + qt * 128) * NTOK;

    int krow = tid >> 2, kch = (tid & 3) * 4;
    int vrow = tid >> 3, vch = (tid & 7) * 4;
    int brow = tid >> 3, bch = (tid & 7) * 8;   // bias: 16B = 8 halves per chunk
#define KVB_LOAD(stage, mt_)                                                      \
    do {                                                                          \
        cp16(&Khs[(stage) * 1280 + krow * 20 + kch], khb + (size_t)((mt_) * 64 + krow) * 16 + kch); \
        cp16(&Kls[(stage) * 1280 + krow * 20 + kch], klb + (size_t)((mt_) * 64 + krow) * 16 + kch); \
        cp16(&Vs[(stage) * 2304 + vrow * 36 + vch], vtb + (size_t)((mt_) * 64 + vrow) * 32 + vch);  \
        cp16(&Vs[(stage) * 2304 + (vrow + 32) * 36 + vch], vtb + (size_t)((mt_) * 64 + vrow + 32) * 32 + vch); \
        _Pragma("unroll")                                                         \
        for (int p = 0; p < 4; p++) {                                             \
            int row = brow + p * 32;                                              \
            cp16(&BBh[(stage) * 9216 + row * 72 + bch],                           \
                 bbh + (size_t)row * NTOK + (mt_) * 64 + bch);                    \
        }                                                                         \
        CP_COMMIT();                                                              \
    } while (0)

    KVB_LOAD(0, 0);

    // Q fragments (bf16 pairs, persist in registers)
    unsigned Qh[2][4], Ql[2][4];
    int r = w * 16 + g;
#pragma unroll
    for (int kt = 0; kt < 2; kt++) {
        int c = kt * 8 + tg;
        Qh[kt][0] = qhb[r * 16 + c];           Ql[kt][0] = qlb[r * 16 + c];
        Qh[kt][1] = qhb[(r + 8) * 16 + c];     Ql[kt][1] = qlb[(r + 8) * 16 + c];
        Qh[kt][2] = qhb[r * 16 + c + 4];       Ql[kt][2] = qlb[r * 16 + c + 4];
        Qh[kt][3] = qhb[(r + 8) * 16 + c + 4]; Ql[kt][3] = qlb[(r + 8) * 16 + c + 4];
    }

    float m0 = -INFINITY, m1 = -INFINITY, l0 = 0.0f, l1 = 0.0f;
    float O[4][4];
#pragma unroll
    for (int j = 0; j < 4; j++)
#pragma unroll
        for (int c = 0; c < 4; c++) O[j][c] = 0.0f;

    for (int mt = 0; mt < 16; mt++) {
        int s = mt & 1;
        CP_WAIT(0);        // group(mt) is the only outstanding group -> tile mt landed
        __syncthreads();   // (A) tile mt visible to all; all warps done with PV(mt-1)
        if (mt + 1 < 16) KVB_LOAD(s ^ 1, mt + 1);   // safe: stage s^1 free after (A)

        // QK^T: 3xBF16
        float S[8][4];
#pragma unroll
        for (int j = 0; j < 8; j++)
#pragma unroll
            for (int c = 0; c < 4; c++) S[j][c] = 0.0f;
        const unsigned* Khb = Khs + s * 1280;
        const unsigned* Klb = Kls + s * 1280;
#pragma unroll
        for (int kt = 0; kt < 2; kt++) {
            int kc = kt * 8 + tg;
#pragma unroll
            for (int j = 0; j < 8; j++) {
                int key = j * 8 + g;
                unsigned bh2[2] = {Khb[key * 20 + kc], Khb[key * 20 + kc + 4]};
                unsigned bl2[2] = {Klb[key * 20 + kc], Klb[key * 20 + kc + 4]};
                mma16(S[j], Qh[kt], bh2);
                mma16(S[j], Qh[kt], bl2);
                mma16(S[j], Ql[kt], bh2);
            }
        }
        // bias add (fp16 -> fp32)
        const __half* Bb = BBh + s * 9216;
#pragma unroll
        for (int j = 0; j < 8; j++) {
            float2 b0 = __half22float2(*(const __half2*)(Bb + r * 72 + j * 8 + tg * 2));
            float2 b1 = __half22float2(*(const __half2*)(Bb + (r + 8) * 72 + j * 8 + tg * 2));
            S[j][0] += b0.x; S[j][1] += b0.y;
            S[j][2] += b1.x; S[j][3] += b1.y;
        }
        // online softmax
        float mx0 = -INFINITY, mx1 = -INFINITY;
#pragma unroll
        for (int j = 0; j < 8; j++) {
            mx0 = fmaxf(mx0, fmaxf(S[j][0], S[j][1]));
            mx1 = fmaxf(mx1, fmaxf(S[j][2], S[j][3]));
        }
        mx0 = fmaxf(mx0, __shfl_xor_sync(0xffffffffu, mx0, 1));
        mx0 = fmaxf(mx0, __shfl_xor_sync(0xffffffffu, mx0, 2));
        mx1 = fmaxf(mx1, __shfl_xor_sync(0xffffffffu, mx1, 1));
        mx1 = fmaxf(mx1, __shfl_xor_sync(0xffffffffu, mx1, 2));
        float mn0 = fmaxf(m0, mx0), mn1 = fmaxf(m1, mx1);
        float alpha0 = __expf(m0 - mn0), alpha1 = __expf(m1 - mn1);
        m0 = mn0; m1 = mn1;
        float rs0 = 0.0f, rs1 = 0.0f;
#pragma unroll
        for (int j = 0; j < 8; j++) {
            S[j][0] = __expf(S[j][0] - mn0);
            S[j][1] = __expf(S[j][1] - mn0);
            S[j][2] = __expf(S[j][2] - mn1);
            S[j][3] = __expf(S[j][3] - mn1);
            rs0 += S[j][0] + S[j][1];
            rs1 += S[j][2] + S[j][3];
        }
        rs0 += __shfl_xor_sync(0xffffffffu, rs0, 1);
        rs0 += __shfl_xor_sync(0xffffffffu, rs0, 2);
        rs1 += __shfl_xor_sync(0xffffffffu, rs1, 1);
        rs1 += __shfl_xor_sync(0xffffffffu, rs1, 2);
        l0 = l0 * alpha0 + rs0;
        l1 = l1 * alpha1 + rs1;
#pragma unroll
        for (int j = 0; j < 4; j++) {
            O[j][0] *= alpha0; O[j][1] *= alpha0;
            O[j][2] *= alpha1; O[j][3] *= alpha1;
        }
        // store P (tf32 bits)  (Pb was last read in PV(mt-1), before barrier (A))
#pragma unroll
        for (int j = 0; j < 8; j++) {
            uint2 p0 = make_uint2(tf32_rna(S[j][0]), tf32_rna(S[j][1]));
            uint2 p1 = make_uint2(tf32_rna(S[j][2]), tf32_rna(S[j][3]));
            *(uint2*)(Pb + r * 68 + j * 8 + tg * 2) = p0;
            *(uint2*)(Pb + (r + 8) * 68 + j * 8 + tg * 2) = p1;
        }
        __syncthreads();   // (B) P visible
        // P @ V (TF32 1x)
        const unsigned* Vb = Vs + s * 2304;
#pragma unroll
        for (int kt = 0; kt < 8; kt++) {
            int kc = kt * 8 + tg;
            unsigned a[4] = {Pb[r * 68 + kc], Pb[(r + 8) * 68 + kc],
                             Pb[r * 68 + kc + 4], Pb[(r + 8) * 68 + kc + 4]};
#pragma unroll
            for (int j = 0; j < 4; j++) {
                unsigned bb[2] = {Vb[kc * 36 + j * 8 + g], Vb[(kc + 4) * 36 + j * 8 + g]};
                mma8t(O[j], a, bb);
            }
        }
    }
    // epilogue: pack bf16 hi/lo pairs for proj GEMM
    float inv0 = 1.0f / l0, inv1 = 1.0f / l1;
    int q0r = qt * 128 + w * 16 + g;
    size_t row0 = (size_t)b * NTOK + q0r;
    int colbase = h * 16;
#pragma unroll
    for (int j = 0; j < 4; j++) {
        unsigned hw, lw;
        bf16_split2(O[j][0] * inv0, O[j][1] * inv0, hw, lw);
        g_oh[row0 * 256 + colbase + j * 4 + tg] = hw;
        g_ol[row0 * 256 + colbase + j * 4 + tg] = lw;
        bf16_split2(O[j][2] * inv1, O[j][3] * inv1, hw, lw);
        g_oh[(row0 + 8) * 256 + colbase + j * 4 + tg] = hw;
        g_ol[(row0 + 8) * 256 + colbase + j * 4 + tg] = lw;
    }
}

// ---------------- launcher ---------------------------------------------------
extern "C" void kernel_launch(void* const* d_in, const int* in_sizes, int n_in,
                              void* d_out, int out_size) {
    const float* x      = (const float*)d_in[0];
    const int*   rpi    = (const int*)d_in[3];
    const float* table  = (const float*)d_in[4];
    const float* qkv_w  = (const float*)d_in[5];
    const float* qkv_b  = (const float*)d_in[6];
    const float* proj_w = (const float*)d_in[7];
    const float* proj_b = (const float*)d_in[8];
    const float* temp   = (const float*)d_in[9];
    const float* qe     = (const float*)d_in[10];
    const float* fc1w   = (const float*)d_in[11];
    const float* fc1b   = (const float*)d_in[12];
    const float* fc2w   = (const float*)d_in[13];
    const float* fc2b   = (const float*)d_in[14];
    float* out = (float*)d_out;

    float* p_qkv;  cudaGetSymbolAddress((void**)&p_qkv,  g_qkv);
    unsigned* p_wh; cudaGetSymbolAddress((void**)&p_wh, g_wh);
    unsigned* p_wl; cudaGetSymbolAddress((void**)&p_wl, g_wl);
    unsigned* p_xh; cudaGetSymbolAddress((void**)&p_xh, g_xh);
    unsigned* p_xl; cudaGetSymbolAddress((void**)&p_xl, g_xl);
    unsigned* p_oh; cudaGetSymbolAddress((void**)&p_oh, g_oh);
    unsigned* p_ol; cudaGetSymbolAddress((void**)&p_ol, g_ol);

    static int attr_set = 0;
    if (!attr_set) {
        cudaFuncSetAttribute(attn7_kernel, cudaFuncAttributeMaxDynamicSharedMemorySize,
                             ATTN_SMEM);
        cudaFuncSetAttribute(gemm3b, cudaFuncAttributeMaxDynamicSharedMemorySize,
                             GEMM_SMEM);
        attr_set = 1;
    }

    split_kernel<<<(NW2 + NX2) / 256, 256>>>(qkv_w, proj_w, x);
    cpb_kernel<<<TABLE_SZ, 512>>>(table, fc1w, fc1b, fc2w, fc2b, temp);
    bias_kernel<<<NTOK, 256>>>(rpi);
    {
        dim3 grid(3 * DIMC / 128, BATCH * NTOK / 128);
        gemm3b<<<grid, 256, GEMM_SMEM>>>(p_xh, p_xl, p_wh, p_wl, qkv_b, p_qkv,
                                         BATCH * NTOK, 3 * DIMC, DIMC);
    }
    reorg_kernel<<<BATCH * NTOK * NH / 8, 256>>>(qe);
    {
        dim3 grid(BATCH, NTOK / 128, NH);
        attn7_kernel<<<grid, 256, ATTN_SMEM>>>();
    }
    {
        dim3 grid(DIMC / 128, BATCH * NTOK / 128);
        gemm3b<<<grid, 256, GEMM_SMEM>>>(p_oh, p_ol, p_wh + 3 * DIMC * DIMC / 2,
                                         p_wl + 3 * DIMC * DIMC / 2, proj_b, out,
                                         BATCH * NTOK, DIMC, DIMC);
    }
}

// round 8
// speedup vs baseline: 1.6254x; 1.0546x over previous
#include <cuda_runtime.h>
#include <cuda_bf16.h>
#include <cuda_fp16.h>
#include <math.h>

// Problem constants
#define BATCH 8
#define NTOK 1024
#define DIMC 512
#define NH 16
#define HD 32
#define TABLE_SZ 3969
#define SEQ_SCALE 6.93147180559945309f  // ln(1024)

// ---------------- scratch (device globals; no allocation allowed) -------------
__device__ float g_scale[NH];
__device__ float g_t[TABLE_SZ * NH];
__device__ __half g_biash[NH * NTOK * NTOK];            // [h][n][m] 32MB fp16
__device__ float g_qkv[BATCH * NTOK * 3 * DIMC];        // 50MB
__device__ unsigned g_qh[BATCH * NH * NTOK * HD / 2];   // q hi, packed bf16 pairs
__device__ unsigned g_ql[BATCH * NH * NTOK * HD / 2];   // q lo
__device__ unsigned g_kh[BATCH * NH * NTOK * HD / 2];   // k hi
__device__ unsigned g_kl[BATCH * NH * NTOK * HD / 2];   // k lo
__device__ unsigned g_vt[BATCH * NH * NTOK * HD];       // v tf32
__device__ unsigned g_oh[BATCH * NTOK * DIMC / 2];      // attn out hi (bf16 pairs)
__device__ unsigned g_ol[BATCH * NTOK * DIMC / 2];      // attn out lo
__device__ unsigned g_xh[BATCH * NTOK * DIMC / 2];      // x hi
__device__ unsigned g_xl[BATCH * NTOK * DIMC / 2];      // x lo
__device__ unsigned g_wh[(3 * DIMC + DIMC) * DIMC / 2]; // W hi (qkv then proj)
__device__ unsigned g_wl[(3 * DIMC + DIMC) * DIMC / 2]; // W lo

// ---------------- helpers -----------------------------------------------------
__device__ __forceinline__ unsigned tf32_rna(float x) {
    unsigned r; asm("cvt.rna.tf32.f32 %0, %1;" : "=r"(r) : "f"(x)); return r;
}
__device__ __forceinline__ void bf16_split2(float e, float o, unsigned& hi, unsigned& lo) {
    __nv_bfloat162 h2 = __floats2bfloat162_rn(e, o);
    hi = *(unsigned*)&h2;
    float re = e - __bfloat162float(h2.x);
    float ro = o - __bfloat162float(h2.y);
    __nv_bfloat162 l2 = __floats2bfloat162_rn(re, ro);
    lo = *(unsigned*)&l2;
}
__device__ __forceinline__ void mma16(float* c, const unsigned* a, const unsigned* b) {
    asm volatile("mma.sync.aligned.m16n8k16.row.col.f32.bf16.bf16.f32 "
                 "{%0,%1,%2,%3}, {%4,%5,%6,%7}, {%8,%9}, {%0,%1,%2,%3};"
                 : "+f"(c[0]), "+f"(c[1]), "+f"(c[2]), "+f"(c[3])
                 : "r"(a[0]), "r"(a[1]), "r"(a[2]), "r"(a[3]),
                   "r"(b[0]), "r"(b[1]));
}
__device__ __forceinline__ void mma8t(float* c, const unsigned* a, const unsigned* b) {
    asm volatile("mma.sync.aligned.m16n8k8.row.col.f32.tf32.tf32.f32 "
                 "{%0,%1,%2,%3}, {%4,%5,%6,%7}, {%8,%9}, {%0,%1,%2,%3};"
                 : "+f"(c[0]), "+f"(c[1]), "+f"(c[2]), "+f"(c[3])
                 : "r"(a[0]), "r"(a[1]), "r"(a[2]), "r"(a[3]),
                   "r"(b[0]), "r"(b[1]));
}
__device__ __forceinline__ void ldsm4(unsigned& r0, unsigned& r1, unsigned& r2,
                                      unsigned& r3, const void* p) {
    unsigned a = (unsigned)__cvta_generic_to_shared(p);
    asm volatile("ldmatrix.sync.aligned.m8n8.x4.shared.b16 {%0,%1,%2,%3}, [%4];"
                 : "=r"(r0), "=r"(r1), "=r"(r2), "=r"(r3) : "r"(a));
}
__device__ __forceinline__ void cp16(void* sdst, const void* gsrc) {
    unsigned u = (unsigned)__cvta_generic_to_shared(sdst);
    asm volatile("cp.async.ca.shared.global [%0], [%1], 16;" :: "r"(u), "l"(gsrc));
}
#define CP_COMMIT() asm volatile("cp.async.commit_group;")
#define CP_WAIT(n)  asm volatile("cp.async.wait_group %0;" :: "n"(n))

// ---------------- fused split: weights + x (bf16 hi/lo pairs) ------------------
#define NW2 (4 * DIMC * DIMC / 2)       // 524288 weight pairs
#define NX2 (BATCH * NTOK * DIMC / 2)   // 2097152 x pairs
__global__ void split_kernel(const float* __restrict__ qkvw,
                             const float* __restrict__ projw,
                             const float* __restrict__ x) {
    int i = blockIdx.x * 256 + threadIdx.x;
    unsigned h, l;
    if (i < NW2) {
        int nq2 = 3 * DIMC * DIMC / 2;
        float2 v = (i < nq2) ? ((const float2*)qkvw)[i] : ((const float2*)projw)[i - nq2];
        bf16_split2(v.x, v.y, h, l);
        g_wh[i] = h; g_wl[i] = l;
    } else {
        int j = i - NW2;
        float2 v = ((const float2*)x)[j];
        bf16_split2(v.x, v.y, h, l);
        g_xh[j] = h; g_xl[j] = l;
    }
}

// ---------------- CPB MLP t[r][h] (+ fused temperature scale) -----------------
__global__ void cpb_kernel(const float* __restrict__ table,
                           const float* __restrict__ fc1w,
                           const float* __restrict__ fc1b,
                           const float* __restrict__ fc2w,
                           const float* __restrict__ fc2b,
                           const float* __restrict__ temp) {
    __shared__ float hid[512];
    int r = blockIdx.x;
    int j = threadIdx.x;
    if (r == 0 && j < NH) {
        float t = temp[j];
        float sp = (t > 20.0f) ? t : log1pf(expf(t));
        g_scale[j] = sp * SEQ_SCALE;
    }
    float c0 = table[r * 2 + 0];
    float c1 = table[r * 2 + 1];
    float hv = c0 * fc1w[j * 2 + 0] + c1 * fc1w[j * 2 + 1] + fc1b[j];
    hid[j] = fmaxf(hv, 0.0f);
    __syncthreads();
    int w = j >> 5;
    int lane = j & 31;
    float acc = 0.0f;
#pragma unroll
    for (int kk = lane; kk < 512; kk += 32) acc += hid[kk] * fc2w[w * 512 + kk];
#pragma unroll
    for (int off = 16; off >= 1; off >>= 1) acc += __shfl_xor_sync(0xffffffffu, acc, off);
    if (lane == 0) g_t[r * NH + w] = acc + fc2b[w];
}

// ---------------- bias gather  biash[h][n][m] = half(t[rpi[n][m]][h]) ---------
__global__ void bias_kernel(const int* __restrict__ rpi) {
    int n = blockIdx.x;
    for (int m = threadIdx.x; m < NTOK; m += blockDim.x) {
        int idx = rpi[n * NTOK + m];
        const float4* tp = (const float4*)(g_t + idx * NH);
        float4 t0 = tp[0], t1 = tp[1], t2 = tp[2], t3 = tp[3];
        float v[16] = {t0.x, t0.y, t0.z, t0.w, t1.x, t1.y, t1.z, t1.w,
                       t2.x, t2.y, t2.z, t2.w, t3.x, t3.y, t3.z, t3.w};
#pragma unroll
        for (int h = 0; h < NH; h++)
            g_biash[((size_t)h * NTOK + n) * NTOK + m] = __float2half(v[h]);
    }
}

// ---------------- 3xBF16 GEMM, cp.async 2-stage, ldmatrix operands -------------
#define GEMM_SMEM (4 * 2 * 128 * 20 * 4)
__global__ __launch_bounds__(256, 2) void gemm3b(const unsigned* __restrict__ Ah,
                                                 const unsigned* __restrict__ Al,
                                                 const unsigned* __restrict__ Wh,
                                                 const unsigned* __restrict__ Wl,
                                                 const float* __restrict__ bias,
                                                 float* __restrict__ C,
                                                 int M, int Nn, int K) {
    extern __shared__ unsigned smg[];
    unsigned* Ahs = smg;               // [2][2560]
    unsigned* Als = smg + 2 * 2560;
    unsigned* Whs = smg + 4 * 2560;
    unsigned* Wls = smg + 6 * 2560;

    int tid = threadIdx.x;
    int wid = tid >> 5, lane = tid & 31;
    int g = lane >> 2, tg = lane & 3;
    int wm = wid & 3, wn = wid >> 2;
    int m0 = blockIdx.y * 128, n0 = blockIdx.x * 128;
    int KU = K >> 1;

    int lrow = tid >> 2, lch = (tid & 3) * 4;
    // ldmatrix lane mappings (u32 offsets into [row][20] layout)
    int a_r = (lane & 15), a_c = (lane >> 4) * 4;              // A x4
    int b_r = (lane >> 4) * 8 + (lane & 7), b_c = ((lane >> 3) & 1) * 4;  // B x4

    float acc[2][8][4];
#pragma unroll
    for (int mi = 0; mi < 2; mi++)
#pragma unroll
        for (int j = 0; j < 8; j++)
#pragma unroll
            for (int c = 0; c < 4; c++) acc[mi][j][c] = 0.0f;

    int nk = K >> 5;
#define G_LOAD(stage, ku0)                                                        \
    do {                                                                          \
        cp16(&Ahs[(stage) * 2560 + lrow * 20 + lch], Ah + (size_t)(m0 + lrow) * KU + (ku0) + lch);          \
        cp16(&Ahs[(stage) * 2560 + (lrow + 64) * 20 + lch], Ah + (size_t)(m0 + lrow + 64) * KU + (ku0) + lch); \
        cp16(&Als[(stage) * 2560 + lrow * 20 + lch], Al + (size_t)(m0 + lrow) * KU + (ku0) + lch);          \
        cp16(&Als[(stage) * 2560 + (lrow + 64) * 20 + lch], Al + (size_t)(m0 + lrow + 64) * KU + (ku0) + lch); \
        cp16(&Whs[(stage) * 2560 + lrow * 20 + lch], Wh + (size_t)(n0 + lrow) * KU + (ku0) + lch);          \
        cp16(&Whs[(stage) * 2560 + (lrow + 64) * 20 + lch], Wh + (size_t)(n0 + lrow + 64) * KU + (ku0) + lch); \
        cp16(&Wls[(stage) * 2560 + lrow * 20 + lch], Wl + (size_t)(n0 + lrow) * KU + (ku0) + lch);          \
        cp16(&Wls[(stage) * 2560 + (lrow + 64) * 20 + lch], Wl + (size_t)(n0 + lrow + 64) * KU + (ku0) + lch); \
        CP_COMMIT();                                                              \
    } while (0)

    G_LOAD(0, 0);

    for (int i = 0; i < nk; i++) {
        if (i + 1 < nk) {
            G_LOAD((i + 1) & 1, (i + 1) << 4);
            CP_WAIT(1);
        } else {
            CP_WAIT(0);
        }
        __syncthreads();
        int s = i & 1;
        const unsigned* Ahb = Ahs + s * 2560;
        const unsigned* Alb = Als + s * 2560;
        const unsigned* Whb = Whs + s * 2560;
        const unsigned* Wlb = Wls + s * 2560;
#pragma unroll
        for (int kt = 0; kt < 2; kt++) {
            unsigned ah[2][4], al[2][4];
#pragma unroll
            for (int mi = 0; mi < 2; mi++) {
                int row = wm * 32 + mi * 16 + a_r;
                int col = kt * 8 + a_c;
                ldsm4(ah[mi][0], ah[mi][1], ah[mi][2], ah[mi][3], &Ahb[row * 20 + col]);
                ldsm4(al[mi][0], al[mi][1], al[mi][2], al[mi][3], &Alb[row * 20 + col]);
            }
#pragma unroll
            for (int jp = 0; jp < 4; jp++) {
                int row = wn * 64 + jp * 16 + b_r;
                int col = kt * 8 + b_c;
                unsigned bh[4], bl[4];
                ldsm4(bh[0], bh[1], bh[2], bh[3], &Whb[row * 20 + col]);
                ldsm4(bl[0], bl[1], bl[2], bl[3], &Wlb[row * 20 + col]);
#pragma unroll
                for (int mi = 0; mi < 2; mi++) {
                    mma16(acc[mi][jp * 2], ah[mi], bh);
                    mma16(acc[mi][jp * 2], ah[mi], bl);
                    mma16(acc[mi][jp * 2], al[mi], bh);
                    mma16(acc[mi][jp * 2 + 1], ah[mi], bh + 2);
                    mma16(acc[mi][jp * 2 + 1], ah[mi], bl + 2);
                    mma16(acc[mi][jp * 2 + 1], al[mi], bh + 2);
                }
            }
        }
        __syncthreads();
    }
#pragma unroll
    for (int j = 0; j < 8; j++) {
        int col = n0 + wn * 64 + j * 8 + tg * 2;
        float2 bv = *(const float2*)(bias + col);
#pragma unroll
        for (int mi = 0; mi < 2; mi++) {
            int row = m0 + wm * 32 + mi * 16 + g;
            float2 o0 = make_float2(acc[mi][j][0] + bv.x, acc[mi][j][1] + bv.y);
            float2 o1 = make_float2(acc[mi][j][2] + bv.x, acc[mi][j][3] + bv.y);
            *(float2*)(C + (size_t)row * Nn + col) = o0;
            *(float2*)(C + (size_t)(row + 8) * Nn + col) = o1;
        }
    }
}

// ---------------- reorg: normalize q/k, bf16-split+pack, v tf32 ----------------
__global__ void reorg_kernel(const float* __restrict__ qe) {
    int wg = blockIdx.x * 8 + (threadIdx.x >> 5);
    int lane = threadIdx.x & 31;
    int h = wg & 15;
    int bn = wg >> 4;
    int b = bn >> 10;
    int n = bn & 1023;
    const float* base = g_qkv + (size_t)bn * (3 * DIMC);
    float q = base[h * HD + lane];
    float k = base[DIMC + h * HD + lane];
    float v = base[2 * DIMC + h * HD + lane];

    float s = q * q;
#pragma unroll
    for (int off = 16; off >= 1; off >>= 1) s += __shfl_xor_sync(0xffffffffu, s, off);
    float qn = q / fmaxf(sqrtf(s), 1e-12f);
    qn = (qn + qe[h * HD + lane]) * g_scale[h];

    s = k * k;
#pragma unroll
    for (int off = 16; off >= 1; off >>= 1) s += __shfl_xor_sync(0xffffffffu, s, off);
    float kn = k / fmaxf(sqrtf(s), 1e-12f);

    __nv_bfloat16 qbh = __float2bfloat16_rn(qn);
    unsigned qhu = (unsigned)__bfloat16_as_ushort(qbh);
    unsigned qlu = (unsigned)__bfloat16_as_ushort(__float2bfloat16_rn(qn - __bfloat162float(qbh)));
    __nv_bfloat16 kbh = __float2bfloat16_rn(kn);
    unsigned khu = (unsigned)__bfloat16_as_ushort(kbh);
    unsigned klu = (unsigned)__bfloat16_as_ushort(__float2bfloat16_rn(kn - __bfloat162float(kbh)));

    unsigned qho = __shfl_down_sync(0xffffffffu, qhu, 1);
    unsigned qlo = __shfl_down_sync(0xffffffffu, qlu, 1);
    unsigned kho = __shfl_down_sync(0xffffffffu, khu, 1);
    unsigned klo = __shfl_down_sync(0xffffffffu, klu, 1);

    size_t rbase = ((size_t)(b * NH + h) * NTOK + n) * (HD / 2);
    if ((lane & 1) == 0) {
        int c = lane >> 1;
        g_qh[rbase + c] = qhu | (qho << 16);
        g_ql[rbase + c] = qlu | (qlo << 16);
        g_kh[rbase + c] = khu | (kho << 16);
        g_kl[rbase + c] = klu | (klo << 16);
    }
    g_vt[((size_t)(b * NH + h) * NTOK + n) * HD + lane] = tf32_rna(v);
}

// ---------------- attention v8: ldmatrix K operands, safe pipeline -------------
// grid (B, N/128, H), 256 threads, 128 queries/block, key tiles 64.
#define ATTN_SMEM ((2560 + 2560 + 4608 + 9216 + 8704) * 4)
__global__ __launch_bounds__(256, 2) void attn8_kernel() {
    extern __shared__ unsigned smu[];
    unsigned* Khs = smu;                     // [2][1280]
    unsigned* Kls = smu + 2560;
    unsigned* Vs  = smu + 5120;              // [2][2304]
    __half*  BBh = (__half*)(smu + 9728);    // [2][128*72]
    unsigned* Pb = smu + 9728 + 9216;        // [128][68]

    int b = blockIdx.x, qt = blockIdx.y, h = blockIdx.z;
    int tid = threadIdx.x;
    int w = tid >> 5, lane = tid & 31;
    int g = lane >> 2, tg = lane & 3;

    size_t bh16 = (size_t)(b * NH + h) * NTOK * (HD / 2);
    const unsigned* qhb = g_qh + bh16 + (size_t)qt * 128 * (HD / 2);
    const unsigned* qlb = g_ql + bh16 + (size_t)qt * 128 * (HD / 2);
    const unsigned* khb = g_kh + bh16;
    const unsigned* klb = g_kl + bh16;
    const unsigned* vtb = g_vt + (size_t)(b * NH + h) * NTOK * HD;
    const __half* bbh = g_biash + ((size_t)h * NTOK + qt * 128) * NTOK;

    int krow = tid >> 2, kch = (tid & 3) * 4;
    int vrow = tid >> 3, vch = (tid & 7) * 4;
    int brow = tid >> 3, bch = (tid & 7) * 8;
    int b_r = (lane >> 4) * 8 + (lane & 7), b_c = ((lane >> 3) & 1) * 4;  // ldmatrix B map
#define KVB_LOAD(stage, mt_)                                                      \
    do {                                                                          \
        cp16(&Khs[(stage) * 1280 + krow * 20 + kch], khb + (size_t)((mt_) * 64 + krow) * 16 + kch); \
        cp16(&Kls[(stage) * 1280 + krow * 20 + kch], klb + (size_t)((mt_) * 64 + krow) * 16 + kch); \
        cp16(&Vs[(stage) * 2304 + vrow * 36 + vch], vtb + (size_t)((mt_) * 64 + vrow) * 32 + vch);  \
        cp16(&Vs[(stage) * 2304 + (vrow + 32) * 36 + vch], vtb + (size_t)((mt_) * 64 + vrow + 32) * 32 + vch); \
        _Pragma("unroll")                                                         \
        for (int p = 0; p < 4; p++) {                                             \
            int row = brow + p * 32;                                              \
            cp16(&BBh[(stage) * 9216 + row * 72 + bch],                           \
                 bbh + (size_t)row * NTOK + (mt_) * 64 + bch);                    \
        }                                                                         \
        CP_COMMIT();                                                              \
    } while (0)

    KVB_LOAD(0, 0);

    unsigned Qh[2][4], Ql[2][4];
    int r = w * 16 + g;
#pragma unroll
    for (int kt = 0; kt < 2; kt++) {
        int c = kt * 8 + tg;
        Qh[kt][0] = qhb[r * 16 + c];           Ql[kt][0] = qlb[r * 16 + c];
        Qh[kt][1] = qhb[(r + 8) * 16 + c];     Ql[kt][1] = qlb[(r + 8) * 16 + c];
        Qh[kt][2] = qhb[r * 16 + c + 4];       Ql[kt][2] = qlb[r * 16 + c + 4];
        Qh[kt][3] = qhb[(r + 8) * 16 + c + 4]; Ql[kt][3] = qlb[(r + 8) * 16 + c + 4];
    }

    float m0 = -INFINITY, m1 = -INFINITY, l0 = 0.0f, l1 = 0.0f;
    float O[4][4];
#pragma unroll
    for (int j = 0; j < 4; j++)
#pragma unroll
        for (int c = 0; c < 4; c++) O[j][c] = 0.0f;

    for (int mt = 0; mt < 16; mt++) {
        int s = mt & 1;
        CP_WAIT(0);
        __syncthreads();   // (A) tile mt visible; all warps done with PV(mt-1)
        if (mt + 1 < 16) KVB_LOAD(s ^ 1, mt + 1);

        // QK^T: 3xBF16 via ldmatrix
        float S[8][4];
#pragma unroll
        for (int j = 0; j < 8; j++)
#pragma unroll
            for (int c = 0; c < 4; c++) S[j][c] = 0.0f;
        const unsigned* Khb = Khs + s * 1280;
        const unsigned* Klb = Kls + s * 1280;
#pragma unroll
        for (int kt = 0; kt < 2; kt++) {
#pragma unroll
            for (int jp = 0; jp < 4; jp++) {
                int row = jp * 16 + b_r;
                int col = kt * 8 + b_c;
                unsigned bh2[4], bl2[4];
                ldsm4(bh2[0], bh2[1], bh2[2], bh2[3], &Khb[row * 20 + col]);
                ldsm4(bl2[0], bl2[1], bl2[2], bl2[3], &Klb[row * 20 + col]);
                mma16(S[jp * 2], Qh[kt], bh2);
                mma16(S[jp * 2], Qh[kt], bl2);
                mma16(S[jp * 2], Ql[kt], bh2);
                mma16(S[jp * 2 + 1], Qh[kt], bh2 + 2);
                mma16(S[jp * 2 + 1], Qh[kt], bl2 + 2);
                mma16(S[jp * 2 + 1], Ql[kt], bh2 + 2);
            }
        }
        // bias add (fp16 -> fp32)
        const __half* Bb = BBh + s * 9216;
#pragma unroll
        for (int j = 0; j < 8; j++) {
            float2 b0 = __half22float2(*(const __half2*)(Bb + r * 72 + j * 8 + tg * 2));
            float2 b1 = __half22float2(*(const __half2*)(Bb + (r + 8) * 72 + j * 8 + tg * 2));
            S[j][0] += b0.x; S[j][1] += b0.y;
            S[j][2] += b1.x; S[j][3] += b1.y;
        }
        // online softmax
        float mx0 = -INFINITY, mx1 = -INFINITY;
#pragma unroll
        for (int j = 0; j < 8; j++) {
            mx0 = fmaxf(mx0, fmaxf(S[j][0], S[j][1]));
            mx1 = fmaxf(mx1, fmaxf(S[j][2], S[j][3]));
        }
        mx0 = fmaxf(mx0, __shfl_xor_sync(0xffffffffu, mx0, 1));
        mx0 = fmaxf(mx0, __shfl_xor_sync(0xffffffffu, mx0, 2));
        mx1 = fmaxf(mx1, __shfl_xor_sync(0xffffffffu, mx1, 1));
        mx1 = fmaxf(mx1, __shfl_xor_sync(0xffffffffu, mx1, 2));
        float mn0 = fmaxf(m0, mx0), mn1 = fmaxf(m1, mx1);
        float alpha0 = __expf(m0 - mn0), alpha1 = __expf(m1 - mn1);
        m0 = mn0; m1 = mn1;
        float rs0 = 0.0f, rs1 = 0.0f;
#pragma unroll
        for (int j = 0; j < 8; j++) {
            S[j][0] = __expf(S[j][0] - mn0);
            S[j][1] = __expf(S[j][1] - mn0);
            S[j][2] = __expf(S[j][2] - mn1);
            S[j][3] = __expf(S[j][3] - mn1);
            rs0 += S[j][0] + S[j][1];
            rs1 += S[j][2] + S[j][3];
        }
        rs0 += __shfl_xor_sync(0xffffffffu, rs0, 1);
        rs0 += __shfl_xor_sync(0xffffffffu, rs0, 2);
        rs1 += __shfl_xor_sync(0xffffffffu, rs1, 1);
        rs1 += __shfl_xor_sync(0xffffffffu, rs1, 2);
        l0 = l0 * alpha0 + rs0;
        l1 = l1 * alpha1 + rs1;
#pragma unroll
        for (int j = 0; j < 4; j++) {
            O[j][0] *= alpha0; O[j][1] *= alpha0;
            O[j][2] *= alpha1; O[j][3] *= alpha1;
        }
        // store P (tf32 bits)
#pragma unroll
        for (int j = 0; j < 8; j++) {
            uint2 p0 = make_uint2(tf32_rna(S[j][0]), tf32_rna(S[j][1]));
            uint2 p1 = make_uint2(tf32_rna(S[j][2]), tf32_rna(S[j][3]));
            *(uint2*)(Pb + r * 68 + j * 8 + tg * 2) = p0;
            *(uint2*)(Pb + (r + 8) * 68 + j * 8 + tg * 2) = p1;
        }
        __syncthreads();   // (B) P visible
        // P @ V (TF32 1x)
        const unsigned* Vb = Vs + s * 2304;
#pragma unroll
        for (int kt = 0; kt < 8; kt++) {
            int kc = kt * 8 + tg;
            unsigned a[4] = {Pb[r * 68 + kc], Pb[(r + 8) * 68 + kc],
                             Pb[r * 68 + kc + 4], Pb[(r + 8) * 68 + kc + 4]};
#pragma unroll
            for (int j = 0; j < 4; j++) {
                unsigned bb[2] = {Vb[kc * 36 + j * 8 + g], Vb[(kc + 4) * 36 + j * 8 + g]};
                mma8t(O[j], a, bb);
            }
        }
    }
    // epilogue: pack bf16 hi/lo pairs for proj GEMM
    float inv0 = 1.0f / l0, inv1 = 1.0f / l1;
    int q0r = qt * 128 + w * 16 + g;
    size_t row0 = (size_t)b * NTOK + q0r;
    int colbase = h * 16;
#pragma unroll
    for (int j = 0; j < 4; j++) {
        unsigned hw, lw;
        bf16_split2(O[j][0] * inv0, O[j][1] * inv0, hw, lw);
        g_oh[row0 * 256 + colbase + j * 4 + tg] = hw;
        g_ol[row0 * 256 + colbase + j * 4 + tg] = lw;
        bf16_split2(O[j][2] * inv1, O[j][3] * inv1, hw, lw);
        g_oh[(row0 + 8) * 256 + colbase + j * 4 + tg] = hw;
        g_ol[(row0 + 8) * 256 + colbase + j * 4 + tg] = lw;
    }
}

// ---------------- launcher ---------------------------------------------------
extern "C" void kernel_launch(void* const* d_in, const int* in_sizes, int n_in,
                              void* d_out, int out_size) {
    const float* x      = (const float*)d_in[0];
    const int*   rpi    = (const int*)d_in[3];
    const float* table  = (const float*)d_in[4];
    const float* qkv_w  = (const float*)d_in[5];
    const float* qkv_b  = (const float*)d_in[6];
    const float* proj_w = (const float*)d_in[7];
    const float* proj_b = (const float*)d_in[8];
    const float* temp   = (const float*)d_in[9];
    const float* qe     = (const float*)d_in[10];
    const float* fc1w   = (const float*)d_in[11];
    const float* fc1b   = (const float*)d_in[12];
    const float* fc2w   = (const float*)d_in[13];
    const float* fc2b   = (const float*)d_in[14];
    float* out = (float*)d_out;

    float* p_qkv;  cudaGetSymbolAddress((void**)&p_qkv,  g_qkv);
    unsigned* p_wh; cudaGetSymbolAddress((void**)&p_wh, g_wh);
    unsigned* p_wl; cudaGetSymbolAddress((void**)&p_wl, g_wl);
    unsigned* p_xh; cudaGetSymbolAddress((void**)&p_xh, g_xh);
    unsigned* p_xl; cudaGetSymbolAddress((void**)&p_xl, g_xl);
    unsigned* p_oh; cudaGetSymbolAddress((void**)&p_oh, g_oh);
    unsigned* p_ol; cudaGetSymbolAddress((void**)&p_ol, g_ol);

    static int attr_set = 0;
    if (!attr_set) {
        cudaFuncSetAttribute(attn8_kernel, cudaFuncAttributeMaxDynamicSharedMemorySize,
                             ATTN_SMEM);
        cudaFuncSetAttribute(gemm3b, cudaFuncAttributeMaxDynamicSharedMemorySize,
                             GEMM_SMEM);
        attr_set = 1;
    }

    split_kernel<<<(NW2 + NX2) / 256, 256>>>(qkv_w, proj_w, x);
    cpb_kernel<<<TABLE_SZ, 512>>>(table, fc1w, fc1b, fc2w, fc2b, temp);
    bias_kernel<<<NTOK, 256>>>(rpi);
    {
        dim3 grid(3 * DIMC / 128, BATCH * NTOK / 128);
        gemm3b<<<grid, 256, GEMM_SMEM>>>(p_xh, p_xl, p_wh, p_wl, qkv_b, p_qkv,
                                         BATCH * NTOK, 3 * DIMC, DIMC);
    }
    reorg_kernel<<<BATCH * NTOK * NH / 8, 256>>>(qe);
    {
        dim3 grid(BATCH, NTOK / 128, NH);
        attn8_kernel<<<grid, 256, ATTN_SMEM>>>();
    }
    {
        dim3 grid(DIMC / 128, BATCH * NTOK / 128);
        gemm3b<<<grid, 256, GEMM_SMEM>>>(p_oh, p_ol, p_wh + 3 * DIMC * DIMC / 2,
                                         p_wl + 3 * DIMC * DIMC / 2, proj_b, out,
                                         BATCH * NTOK, DIMC, DIMC);
    }
}

// round 9
// speedup vs baseline: 1.6410x; 1.0096x over previous
#include <cuda_runtime.h>
#include <cuda_bf16.h>
#include <cuda_fp16.h>
#include <math.h>

// Problem constants
#define BATCH 8
#define NTOK 1024
#define DIMC 512
#define NH 16
#define HD 32
#define TABLE_SZ 3969
#define SEQ_SCALE 6.93147180559945309f  // ln(1024)

// ---------------- scratch (device globals; no allocation allowed) -------------
__device__ float g_scale[NH];
__device__ float g_t[TABLE_SZ * NH];
__device__ __half g_biash[NH * NTOK * NTOK];            // [h][n][m] 32MB fp16
__device__ float g_qkv[BATCH * NTOK * 3 * DIMC];        // 50MB
__device__ unsigned g_qh[BATCH * NH * NTOK * HD / 2];   // q hi, packed bf16 pairs
__device__ unsigned g_ql[BATCH * NH * NTOK * HD / 2];   // q lo
__device__ unsigned g_kh[BATCH * NH * NTOK * HD / 2];   // k hi
__device__ unsigned g_kl[BATCH * NH * NTOK * HD / 2];   // k lo
__device__ unsigned g_vt[BATCH * NH * NTOK * HD];       // v tf32
__device__ unsigned g_oh[BATCH * NTOK * DIMC / 2];      // attn out hi (bf16 pairs)
__device__ unsigned g_ol[BATCH * NTOK * DIMC / 2];      // attn out lo
__device__ unsigned g_xh[BATCH * NTOK * DIMC / 2];      // x hi
__device__ unsigned g_xl[BATCH * NTOK * DIMC / 2];      // x lo
__device__ unsigned g_wh[(3 * DIMC + DIMC) * DIMC / 2]; // W hi (qkv then proj)
__device__ unsigned g_wl[(3 * DIMC + DIMC) * DIMC / 2]; // W lo

// ---------------- helpers -----------------------------------------------------
__device__ __forceinline__ unsigned tf32_rna(float x) {
    unsigned r; asm("cvt.rna.tf32.f32 %0, %1;" : "=r"(r) : "f"(x)); return r;
}
__device__ __forceinline__ void bf16_split2(float e, float o, unsigned& hi, unsigned& lo) {
    __nv_bfloat162 h2 = __floats2bfloat162_rn(e, o);
    hi = *(unsigned*)&h2;
    float re = e - __bfloat162float(h2.x);
    float ro = o - __bfloat162float(h2.y);
    __nv_bfloat162 l2 = __floats2bfloat162_rn(re, ro);
    lo = *(unsigned*)&l2;
}
__device__ __forceinline__ void mma16(float* c, const unsigned* a, const unsigned* b) {
    asm volatile("mma.sync.aligned.m16n8k16.row.col.f32.bf16.bf16.f32 "
                 "{%0,%1,%2,%3}, {%4,%5,%6,%7}, {%8,%9}, {%0,%1,%2,%3};"
                 : "+f"(c[0]), "+f"(c[1]), "+f"(c[2]), "+f"(c[3])
                 : "r"(a[0]), "r"(a[1]), "r"(a[2]), "r"(a[3]),
                   "r"(b[0]), "r"(b[1]));
}
__device__ __forceinline__ void mma8t(float* c, const unsigned* a, const unsigned* b) {
    asm volatile("mma.sync.aligned.m16n8k8.row.col.f32.tf32.tf32.f32 "
                 "{%0,%1,%2,%3}, {%4,%5,%6,%7}, {%8,%9}, {%0,%1,%2,%3};"
                 : "+f"(c[0]), "+f"(c[1]), "+f"(c[2]), "+f"(c[3])
                 : "r"(a[0]), "r"(a[1]), "r"(a[2]), "r"(a[3]),
                   "r"(b[0]), "r"(b[1]));
}
__device__ __forceinline__ void ldsm4(unsigned& r0, unsigned& r1, unsigned& r2,
                                      unsigned& r3, const void* p) {
    unsigned a = (unsigned)__cvta_generic_to_shared(p);
    asm volatile("ldmatrix.sync.aligned.m8n8.x4.shared.b16 {%0,%1,%2,%3}, [%4];"
                 : "=r"(r0), "=r"(r1), "=r"(r2), "=r"(r3) : "r"(a));
}
__device__ __forceinline__ void cp16(void* sdst, const void* gsrc) {
    unsigned u = (unsigned)__cvta_generic_to_shared(sdst);
    asm volatile("cp.async.ca.shared.global [%0], [%1], 16;" :: "r"(u), "l"(gsrc));
}
#define CP_COMMIT() asm volatile("cp.async.commit_group;")
#define CP_WAIT(n)  asm volatile("cp.async.wait_group %0;" :: "n"(n))

// ---------------- fused split: weights + x (bf16 hi/lo pairs) ------------------
#define NW2 (4 * DIMC * DIMC / 2)       // 524288 weight pairs
#define NX2 (BATCH * NTOK * DIMC / 2)   // 2097152 x pairs
__global__ void split_kernel(const float* __restrict__ qkvw,
                             const float* __restrict__ projw,
                             const float* __restrict__ x) {
    int i = blockIdx.x * 256 + threadIdx.x;
    unsigned h, l;
    if (i < NW2) {
        int nq2 = 3 * DIMC * DIMC / 2;
        float2 v = (i < nq2) ? ((const float2*)qkvw)[i] : ((const float2*)projw)[i - nq2];
        bf16_split2(v.x, v.y, h, l);
        g_wh[i] = h; g_wl[i] = l;
    } else {
        int j = i - NW2;
        float2 v = ((const float2*)x)[j];
        bf16_split2(v.x, v.y, h, l);
        g_xh[j] = h; g_xl[j] = l;
    }
}

// ---------------- CPB MLP t[r][h] (+ fused temperature scale) -----------------
__global__ void cpb_kernel(const float* __restrict__ table,
                           const float* __restrict__ fc1w,
                           const float* __restrict__ fc1b,
                           const float* __restrict__ fc2w,
                           const float* __restrict__ fc2b,
                           const float* __restrict__ temp) {
    __shared__ float hid[512];
    int r = blockIdx.x;
    int j = threadIdx.x;
    if (r == 0 && j < NH) {
        float t = temp[j];
        float sp = (t > 20.0f) ? t : log1pf(expf(t));
        g_scale[j] = sp * SEQ_SCALE;
    }
    float c0 = table[r * 2 + 0];
    float c1 = table[r * 2 + 1];
    float hv = c0 * fc1w[j * 2 + 0] + c1 * fc1w[j * 2 + 1] + fc1b[j];
    hid[j] = fmaxf(hv, 0.0f);
    __syncthreads();
    int w = j >> 5;
    int lane = j & 31;
    float acc = 0.0f;
#pragma unroll
    for (int kk = lane; kk < 512; kk += 32) acc += hid[kk] * fc2w[w * 512 + kk];
#pragma unroll
    for (int off = 16; off >= 1; off >>= 1) acc += __shfl_xor_sync(0xffffffffu, acc, off);
    if (lane == 0) g_t[r * NH + w] = acc + fc2b[w];
}

// ---------------- bias gather  biash[h][n][m] = half(t[rpi[n][m]][h]) ---------
__global__ void bias_kernel(const int* __restrict__ rpi) {
    int n = blockIdx.x;
    for (int m = threadIdx.x; m < NTOK; m += blockDim.x) {
        int idx = rpi[n * NTOK + m];
        const float4* tp = (const float4*)(g_t + idx * NH);
        float4 t0 = tp[0], t1 = tp[1], t2 = tp[2], t3 = tp[3];
        float v[16] = {t0.x, t0.y, t0.z, t0.w, t1.x, t1.y, t1.z, t1.w,
                       t2.x, t2.y, t2.z, t2.w, t3.x, t3.y, t3.z, t3.w};
#pragma unroll
        for (int h = 0; h < NH; h++)
            g_biash[((size_t)h * NTOK + n) * NTOK + m] = __float2half(v[h]);
    }
}

// ---------------- 3xBF16 GEMM, cp.async 2-stage, pipelined ldmatrix ------------
#define GEMM_SMEM (4 * 2 * 128 * 20 * 4)
__global__ __launch_bounds__(256, 2) void gemm3b(const unsigned* __restrict__ Ah,
                                                 const unsigned* __restrict__ Al,
                                                 const unsigned* __restrict__ Wh,
                                                 const unsigned* __restrict__ Wl,
                                                 const float* __restrict__ bias,
                                                 float* __restrict__ C,
                                                 int M, int Nn, int K) {
    extern __shared__ unsigned smg[];
    unsigned* Ahs = smg;               // [2][2560]
    unsigned* Als = smg + 2 * 2560;
    unsigned* Whs = smg + 4 * 2560;
    unsigned* Wls = smg + 6 * 2560;

    int tid = threadIdx.x;
    int wid = tid >> 5, lane = tid & 31;
    int g = lane >> 2, tg = lane & 3;
    int wm = wid & 3, wn = wid >> 2;
    int m0 = blockIdx.y * 128, n0 = blockIdx.x * 128;
    int KU = K >> 1;

    int lrow = tid >> 2, lch = (tid & 3) * 4;
    int a_r = (lane & 15), a_c = (lane >> 4) * 4;              // A ldmatrix map
    int b_r = (lane >> 4) * 8 + (lane & 7), b_c = ((lane >> 3) & 1) * 4;  // B map

    float acc[2][8][4];
#pragma unroll
    for (int mi = 0; mi < 2; mi++)
#pragma unroll
        for (int j = 0; j < 8; j++)
#pragma unroll
            for (int c = 0; c < 4; c++) acc[mi][j][c] = 0.0f;

    int nk = K >> 5;
#define G_LOAD(stage, ku0)                                                        \
    do {                                                                          \
        cp16(&Ahs[(stage) * 2560 + lrow * 20 + lch], Ah + (size_t)(m0 + lrow) * KU + (ku0) + lch);          \
        cp16(&Ahs[(stage) * 2560 + (lrow + 64) * 20 + lch], Ah + (size_t)(m0 + lrow + 64) * KU + (ku0) + lch); \
        cp16(&Als[(stage) * 2560 + lrow * 20 + lch], Al + (size_t)(m0 + lrow) * KU + (ku0) + lch);          \
        cp16(&Als[(stage) * 2560 + (lrow + 64) * 20 + lch], Al + (size_t)(m0 + lrow + 64) * KU + (ku0) + lch); \
        cp16(&Whs[(stage) * 2560 + lrow * 20 + lch], Wh + (size_t)(n0 + lrow) * KU + (ku0) + lch);          \
        cp16(&Whs[(stage) * 2560 + (lrow + 64) * 20 + lch], Wh + (size_t)(n0 + lrow + 64) * KU + (ku0) + lch); \
        cp16(&Wls[(stage) * 2560 + lrow * 20 + lch], Wl + (size_t)(n0 + lrow) * KU + (ku0) + lch);          \
        cp16(&Wls[(stage) * 2560 + (lrow + 64) * 20 + lch], Wl + (size_t)(n0 + lrow + 64) * KU + (ku0) + lch); \
        CP_COMMIT();                                                              \
    } while (0)

    G_LOAD(0, 0);

    for (int i = 0; i < nk; i++) {
        if (i + 1 < nk) {
            G_LOAD((i + 1) & 1, (i + 1) << 4);
            CP_WAIT(1);
        } else {
            CP_WAIT(0);
        }
        __syncthreads();
        int s = i & 1;
        const unsigned* Ahb = Ahs + s * 2560;
        const unsigned* Alb = Als + s * 2560;
        const unsigned* Whb = Whs + s * 2560;
        const unsigned* Wlb = Wls + s * 2560;
#pragma unroll
        for (int kt = 0; kt < 2; kt++) {
            // A fragments for this kt
            unsigned ah[2][4], al[2][4];
#pragma unroll
            for (int mi = 0; mi < 2; mi++) {
                int row = wm * 32 + mi * 16 + a_r;
                int col = kt * 8 + a_c;
                ldsm4(ah[mi][0], ah[mi][1], ah[mi][2], ah[mi][3], &Ahb[row * 20 + col]);
                ldsm4(al[mi][0], al[mi][1], al[mi][2], al[mi][3], &Alb[row * 20 + col]);
            }
            // B fragments double-buffered: prefetch jp+1 before jp's MMAs
            unsigned bh[2][4], bl[2][4];
            {
                int row = wn * 64 + b_r;
                int col = kt * 8 + b_c;
                ldsm4(bh[0][0], bh[0][1], bh[0][2], bh[0][3], &Whb[row * 20 + col]);
                ldsm4(bl[0][0], bl[0][1], bl[0][2], bl[0][3], &Wlb[row * 20 + col]);
            }
#pragma unroll
            for (int jp = 0; jp < 4; jp++) {
                int cur = jp & 1;
                if (jp < 3) {
                    int row = wn * 64 + (jp + 1) * 16 + b_r;
                    int col = kt * 8 + b_c;
                    ldsm4(bh[cur ^ 1][0], bh[cur ^ 1][1], bh[cur ^ 1][2], bh[cur ^ 1][3],
                          &Whb[row * 20 + col]);
                    ldsm4(bl[cur ^ 1][0], bl[cur ^ 1][1], bl[cur ^ 1][2], bl[cur ^ 1][3],
                          &Wlb[row * 20 + col]);
                }
#pragma unroll
                for (int mi = 0; mi < 2; mi++) {
                    mma16(acc[mi][jp * 2], ah[mi], bh[cur]);
                    mma16(acc[mi][jp * 2], ah[mi], bl[cur]);
                    mma16(acc[mi][jp * 2], al[mi], bh[cur]);
                    mma16(acc[mi][jp * 2 + 1], ah[mi], bh[cur] + 2);
                    mma16(acc[mi][jp * 2 + 1], ah[mi], bl[cur] + 2);
                    mma16(acc[mi][jp * 2 + 1], al[mi], bh[cur] + 2);
                }
            }
        }
        __syncthreads();
    }
#pragma unroll
    for (int j = 0; j < 8; j++) {
        int col = n0 + wn * 64 + j * 8 + tg * 2;
        float2 bv = *(const float2*)(bias + col);
#pragma unroll
        for (int mi = 0; mi < 2; mi++) {
            int row = m0 + wm * 32 + mi * 16 + g;
            float2 o0 = make_float2(acc[mi][j][0] + bv.x, acc[mi][j][1] + bv.y);
            float2 o1 = make_float2(acc[mi][j][2] + bv.x, acc[mi][j][3] + bv.y);
            *(float2*)(C + (size_t)row * Nn + col) = o0;
            *(float2*)(C + (size_t)(row + 8) * Nn + col) = o1;
        }
    }
}

// ---------------- reorg: normalize q/k, bf16-split+pack, v tf32 ----------------
__global__ void reorg_kernel(const float* __restrict__ qe) {
    int wg = blockIdx.x * 8 + (threadIdx.x >> 5);
    int lane = threadIdx.x & 31;
    int h = wg & 15;
    int bn = wg >> 4;
    int b = bn >> 10;
    int n = bn & 1023;
    const float* base = g_qkv + (size_t)bn * (3 * DIMC);
    float q = base[h * HD + lane];
    float k = base[DIMC + h * HD + lane];
    float v = base[2 * DIMC + h * HD + lane];

    float s = q * q;
#pragma unroll
    for (int off = 16; off >= 1; off >>= 1) s += __shfl_xor_sync(0xffffffffu, s, off);
    float qn = q / fmaxf(sqrtf(s), 1e-12f);
    qn = (qn + qe[h * HD + lane]) * g_scale[h];

    s = k * k;
#pragma unroll
    for (int off = 16; off >= 1; off >>= 1) s += __shfl_xor_sync(0xffffffffu, s, off);
    float kn = k / fmaxf(sqrtf(s), 1e-12f);

    __nv_bfloat16 qbh = __float2bfloat16_rn(qn);
    unsigned qhu = (unsigned)__bfloat16_as_ushort(qbh);
    unsigned qlu = (unsigned)__bfloat16_as_ushort(__float2bfloat16_rn(qn - __bfloat162float(qbh)));
    __nv_bfloat16 kbh = __float2bfloat16_rn(kn);
    unsigned khu = (unsigned)__bfloat16_as_ushort(kbh);
    unsigned klu = (unsigned)__bfloat16_as_ushort(__float2bfloat16_rn(kn - __bfloat162float(kbh)));

    unsigned qho = __shfl_down_sync(0xffffffffu, qhu, 1);
    unsigned qlo = __shfl_down_sync(0xffffffffu, qlu, 1);
    unsigned kho = __shfl_down_sync(0xffffffffu, khu, 1);
    unsigned klo = __shfl_down_sync(0xffffffffu, klu, 1);

    size_t rbase = ((size_t)(b * NH + h) * NTOK + n) * (HD / 2);
    if ((lane & 1) == 0) {
        int c = lane >> 1;
        g_qh[rbase + c] = qhu | (qho << 16);
        g_ql[rbase + c] = qlu | (qlo << 16);
        g_kh[rbase + c] = khu | (kho << 16);
        g_kl[rbase + c] = klu | (klo << 16);
    }
    g_vt[((size_t)(b * NH + h) * NTOK + n) * HD + lane] = tf32_rna(v);
}

// ---------------- attention v9: pipelined ldmatrix QK, safe pipeline -----------
// grid (B, N/128, H), 256 threads, 128 queries/block, key tiles 64.
#define ATTN_SMEM ((2560 + 2560 + 4608 + 9216 + 8704) * 4)
__global__ __launch_bounds__(256, 2) void attn9_kernel() {
    extern __shared__ unsigned smu[];
    unsigned* Khs = smu;                     // [2][1280]
    unsigned* Kls = smu + 2560;
    unsigned* Vs  = smu + 5120;              // [2][2304]
    __half*  BBh = (__half*)(smu + 9728);    // [2][128*72]
    unsigned* Pb = smu + 9728 + 9216;        // [128][68]

    int b = blockIdx.x, qt = blockIdx.y, h = blockIdx.z;
    int tid = threadIdx.x;
    int w = tid >> 5, lane = tid & 31;
    int g = lane >> 2, tg = lane & 3;

    size_t bh16 = (size_t)(b * NH + h) * NTOK * (HD / 2);
    const unsigned* qhb = g_qh + bh16 + (size_t)qt * 128 * (HD / 2);
    const unsigned* qlb = g_ql + bh16 + (size_t)qt * 128 * (HD / 2);
    const unsigned* khb = g_kh + bh16;
    const unsigned* klb = g_kl + bh16;
    const unsigned* vtb = g_vt + (size_t)(b * NH + h) * NTOK * HD;
    const __half* bbh = g_biash + ((size_t)h * NTOK + qt * 128) * NTOK;

    int krow = tid >> 2, kch = (tid & 3) * 4;
    int vrow = tid >> 3, vch = (tid & 7) * 4;
    int brow = tid >> 3, bch = (tid & 7) * 8;
    int b_r = (lane >> 4) * 8 + (lane & 7), b_c = ((lane >> 3) & 1) * 4;
#define KVB_LOAD(stage, mt_)                                                      \
    do {                                                                          \
        cp16(&Khs[(stage) * 1280 + krow * 20 + kch], khb + (size_t)((mt_) * 64 + krow) * 16 + kch); \
        cp16(&Kls[(stage) * 1280 + krow * 20 + kch], klb + (size_t)((mt_) * 64 + krow) * 16 + kch); \
        cp16(&Vs[(stage) * 2304 + vrow * 36 + vch], vtb + (size_t)((mt_) * 64 + vrow) * 32 + vch);  \
        cp16(&Vs[(stage) * 2304 + (vrow + 32) * 36 + vch], vtb + (size_t)((mt_) * 64 + vrow + 32) * 32 + vch); \
        _Pragma("unroll")                                                         \
        for (int p = 0; p < 4; p++) {                                             \
            int row = brow + p * 32;                                              \
            cp16(&BBh[(stage) * 9216 + row * 72 + bch],                           \
                 bbh + (size_t)row * NTOK + (mt_) * 64 + bch);                    \
        }                                                                         \
        CP_COMMIT();                                                              \
    } while (0)

    KVB_LOAD(0, 0);

    unsigned Qh[2][4], Ql[2][4];
    int r = w * 16 + g;
#pragma unroll
    for (int kt = 0; kt < 2; kt++) {
        int c = kt * 8 + tg;
        Qh[kt][0] = qhb[r * 16 + c];           Ql[kt][0] = qlb[r * 16 + c];
        Qh[kt][1] = qhb[(r + 8) * 16 + c];     Ql[kt][1] = qlb[(r + 8) * 16 + c];
        Qh[kt][2] = qhb[r * 16 + c + 4];       Ql[kt][2] = qlb[r * 16 + c + 4];
        Qh[kt][3] = qhb[(r + 8) * 16 + c + 4]; Ql[kt][3] = qlb[(r + 8) * 16 + c + 4];
    }

    float m0 = -INFINITY, m1 = -INFINITY, l0 = 0.0f, l1 = 0.0f;
    float O[4][4];
#pragma unroll
    for (int j = 0; j < 4; j++)
#pragma unroll
        for (int c = 0; c < 4; c++) O[j][c] = 0.0f;

    for (int mt = 0; mt < 16; mt++) {
        int s = mt & 1;
        CP_WAIT(0);
        __syncthreads();   // (A) tile mt visible; all warps done with PV(mt-1)
        if (mt + 1 < 16) KVB_LOAD(s ^ 1, mt + 1);

        // QK^T: 3xBF16, B fragments double-buffered across (kt,jp)
        float S[8][4];
#pragma unroll
        for (int j = 0; j < 8; j++)
#pragma unroll
            for (int c = 0; c < 4; c++) S[j][c] = 0.0f;
        const unsigned* Khb = Khs + s * 1280;
        const unsigned* Klb = Kls + s * 1280;
        unsigned bh2[2][4], bl2[2][4];
        {
            int row = b_r, col = b_c;   // kt=0, jp=0
            ldsm4(bh2[0][0], bh2[0][1], bh2[0][2], bh2[0][3], &Khb[row * 20 + col]);
            ldsm4(bl2[0][0], bl2[0][1], bl2[0][2], bl2[0][3], &Klb[row * 20 + col]);
        }
#pragma unroll
        for (int u = 0; u < 8; u++) {      // u = kt*4 + jp
            int kt = u >> 2, jp = u & 3;
            int cur = u & 1;
            if (u < 7) {
                int nkt = (u + 1) >> 2, njp = (u + 1) & 3;
                int row = njp * 16 + b_r;
                int col = nkt * 8 + b_c;
                ldsm4(bh2[cur ^ 1][0], bh2[cur ^ 1][1], bh2[cur ^ 1][2], bh2[cur ^ 1][3],
                      &Khb[row * 20 + col]);
                ldsm4(bl2[cur ^ 1][0], bl2[cur ^ 1][1], bl2[cur ^ 1][2], bl2[cur ^ 1][3],
                      &Klb[row * 20 + col]);
            }
            mma16(S[jp * 2], Qh[kt], bh2[cur]);
            mma16(S[jp * 2], Qh[kt], bl2[cur]);
            mma16(S[jp * 2], Ql[kt], bh2[cur]);
            mma16(S[jp * 2 + 1], Qh[kt], bh2[cur] + 2);
            mma16(S[jp * 2 + 1], Qh[kt], bl2[cur] + 2);
            mma16(S[jp * 2 + 1], Ql[kt], bh2[cur] + 2);
        }
        // bias add (fp16 -> fp32)
        const __half* Bb = BBh + s * 9216;
#pragma unroll
        for (int j = 0; j < 8; j++) {
            float2 b0 = __half22float2(*(const __half2*)(Bb + r * 72 + j * 8 + tg * 2));
            float2 b1 = __half22float2(*(const __half2*)(Bb + (r + 8) * 72 + j * 8 + tg * 2));
            S[j][0] += b0.x; S[j][1] += b0.y;
            S[j][2] += b1.x; S[j][3] += b1.y;
        }
        // online softmax
        float mx0 = -INFINITY, mx1 = -INFINITY;
#pragma unroll
        for (int j = 0; j < 8; j++) {
            mx0 = fmaxf(mx0, fmaxf(S[j][0], S[j][1]));
            mx1 = fmaxf(mx1, fmaxf(S[j][2], S[j][3]));
        }
        mx0 = fmaxf(mx0, __shfl_xor_sync(0xffffffffu, mx0, 1));
        mx0 = fmaxf(mx0, __shfl_xor_sync(0xffffffffu, mx0, 2));
        mx1 = fmaxf(mx1, __shfl_xor_sync(0xffffffffu, mx1, 1));
        mx1 = fmaxf(mx1, __shfl_xor_sync(0xffffffffu, mx1, 2));
        float mn0 = fmaxf(m0, mx0), mn1 = fmaxf(m1, mx1);
        float alpha0 = __expf(m0 - mn0), alpha1 = __expf(m1 - mn1);
        m0 = mn0; m1 = mn1;
        float rs0 = 0.0f, rs1 = 0.0f;
#pragma unroll
        for (int j = 0; j < 8; j++) {
            S[j][0] = __expf(S[j][0] - mn0);
            S[j][1] = __expf(S[j][1] - mn0);
            S[j][2] = __expf(S[j][2] - mn1);
            S[j][3] = __expf(S[j][3] - mn1);
            rs0 += S[j][0] + S[j][1];
            rs1 += S[j][2] + S[j][3];
        }
        rs0 += __shfl_xor_sync(0xffffffffu, rs0, 1);
        rs0 += __shfl_xor_sync(0xffffffffu, rs0, 2);
        rs1 += __shfl_xor_sync(0xffffffffu, rs1, 1);
        rs1 += __shfl_xor_sync(0xffffffffu, rs1, 2);
        l0 = l0 * alpha0 + rs0;
        l1 = l1 * alpha1 + rs1;
#pragma unroll
        for (int j = 0; j < 4; j++) {
            O[j][0] *= alpha0; O[j][1] *= alpha0;
            O[j][2] *= alpha1; O[j][3] *= alpha1;
        }
        // store P (tf32 bits)
#pragma unroll
        for (int j = 0; j < 8; j++) {
            uint2 p0 = make_uint2(tf32_rna(S[j][0]), tf32_rna(S[j][1]));
            uint2 p1 = make_uint2(tf32_rna(S[j][2]), tf32_rna(S[j][3]));
            *(uint2*)(Pb + r * 68 + j * 8 + tg * 2) = p0;
            *(uint2*)(Pb + (r + 8) * 68 + j * 8 + tg * 2) = p1;
        }
        __syncthreads();   // (B) P visible
        // P @ V (TF32 1x)
        const unsigned* Vb = Vs + s * 2304;
#pragma unroll
        for (int kt = 0; kt < 8; kt++) {
            int kc = kt * 8 + tg;
            unsigned a[4] = {Pb[r * 68 + kc], Pb[(r + 8) * 68 + kc],
                             Pb[r * 68 + kc + 4], Pb[(r + 8) * 68 + kc + 4]};
#pragma unroll
            for (int j = 0; j < 4; j++) {
                unsigned bb[2] = {Vb[kc * 36 + j * 8 + g], Vb[(kc + 4) * 36 + j * 8 + g]};
                mma8t(O[j], a, bb);
            }
        }
    }
    // epilogue: pack bf16 hi/lo pairs for proj GEMM
    float inv0 = 1.0f / l0, inv1 = 1.0f / l1;
    int q0r = qt * 128 + w * 16 + g;
    size_t row0 = (size_t)b * NTOK + q0r;
    int colbase = h * 16;
#pragma unroll
    for (int j = 0; j < 4; j++) {
        unsigned hw, lw;
        bf16_split2(O[j][0] * inv0, O[j][1] * inv0, hw, lw);
        g_oh[row0 * 256 + colbase + j * 4 + tg] = hw;
        g_ol[row0 * 256 + colbase + j * 4 + tg] = lw;
        bf16_split2(O[j][2] * inv1, O[j][3] * inv1, hw, lw);
        g_oh[(row0 + 8) * 256 + colbase + j * 4 + tg] = hw;
        g_ol[(row0 + 8) * 256 + colbase + j * 4 + tg] = lw;
    }
}

// ---------------- launcher ---------------------------------------------------
extern "C" void kernel_launch(void* const* d_in, const int* in_sizes, int n_in,
                              void* d_out, int out_size) {
    const float* x      = (const float*)d_in[0];
    const int*   rpi    = (const int*)d_in[3];
    const float* table  = (const float*)d_in[4];
    const float* qkv_w  = (const float*)d_in[5];
    const float* qkv_b  = (const float*)d_in[6];
    const float* proj_w = (const float*)d_in[7];
    const float* proj_b = (const float*)d_in[8];
    const float* temp   = (const float*)d_in[9];
    const float* qe     = (const float*)d_in[10];
    const float* fc1w   = (const float*)d_in[11];
    const float* fc1b   = (const float*)d_in[12];
    const float* fc2w   = (const float*)d_in[13];
    const float* fc2b   = (const float*)d_in[14];
    float* out = (float*)d_out;

    float* p_qkv;  cudaGetSymbolAddress((void**)&p_qkv,  g_qkv);
    unsigned* p_wh; cudaGetSymbolAddress((void**)&p_wh, g_wh);
    unsigned* p_wl; cudaGetSymbolAddress((void**)&p_wl, g_wl);
    unsigned* p_xh; cudaGetSymbolAddress((void**)&p_xh, g_xh);
    unsigned* p_xl; cudaGetSymbolAddress((void**)&p_xl, g_xl);
    unsigned* p_oh; cudaGetSymbolAddress((void**)&p_oh, g_oh);
    unsigned* p_ol; cudaGetSymbolAddress((void**)&p_ol, g_ol);

    static int attr_set = 0;
    if (!attr_set) {
        cudaFuncSetAttribute(attn9_kernel, cudaFuncAttributeMaxDynamicSharedMemorySize,
                             ATTN_SMEM);
        cudaFuncSetAttribute(gemm3b, cudaFuncAttributeMaxDynamicSharedMemorySize,
                             GEMM_SMEM);
        attr_set = 1;
    }

    split_kernel<<<(NW2 + NX2) / 256, 256>>>(qkv_w, proj_w, x);
    cpb_kernel<<<TABLE_SZ, 512>>>(table, fc1w, fc1b, fc2w, fc2b, temp);
    bias_kernel<<<NTOK, 256>>>(rpi);
    {
        dim3 grid(3 * DIMC / 128, BATCH * NTOK / 128);
        gemm3b<<<grid, 256, GEMM_SMEM>>>(p_xh, p_xl, p_wh, p_wl, qkv_b, p_qkv,
                                         BATCH * NTOK, 3 * DIMC, DIMC);
    }
    reorg_kernel<<<BATCH * NTOK * NH / 8, 256>>>(qe);
    {
        dim3 grid(BATCH, NTOK / 128, NH);
        attn9_kernel<<<grid, 256, ATTN_SMEM>>>();
    }
    {
        dim3 grid(DIMC / 128, BATCH * NTOK / 128);
        gemm3b<<<grid, 256, GEMM_SMEM>>>(p_oh, p_ol, p_wh + 3 * DIMC * DIMC / 2,
                                         p_wl + 3 * DIMC * DIMC / 2, proj_b, out,
                                         BATCH * NTOK, DIMC, DIMC);
    }
}